// round 3
// baseline (speedup 1.0000x reference)
#include <cuda_runtime.h>
#include <math.h>

// b=8, c=192, h=w=128, heads=8, ch=24, hw=16384, 3c=576
#define HW 16384
#define C3 576
#define CC 192
#define NB 8
#define QKCH 16   // split-K chunks for qk

// Scratch (allocation-free rule: __device__ globals)
__device__ float g_qkv_pre[75497472];    // [8,576,16384]
__device__ float g_qkv_post[75497472];   // [8,576,16384]
__device__ float g_sumsq[8 * 384];       // q,k channel sum-of-squares
__device__ float g_Spart[64 * QKCH * 576]; // split-K partials of q.k^T
__device__ float g_W2[8 * 192 * 192];    // folded proj x attn matrix per batch

// ---------------------------------------------------------------------------
// Packed f32x2 helpers (Blackwell: 2 fp32 FMAs per instruction)
__device__ __forceinline__ unsigned long long splat2(float v) {
    unsigned long long r;
    asm("mov.b64 %0, {%1, %1};" : "=l"(r) : "r"(__float_as_uint(v)));
    return r;
}
__device__ __forceinline__ void fma2(unsigned long long& acc,
                                     unsigned long long a, unsigned long long b) {
    asm("fma.rn.f32x2 %0, %1, %2, %0;" : "+l"(acc) : "l"(a), "l"(b));
}
__device__ __forceinline__ float2 unpack2(unsigned long long p) {
    unsigned lo, hi;
    asm("mov.b64 {%0, %1}, %2;" : "=r"(lo), "=r"(hi) : "l"(p));
    return make_float2(__uint_as_float(lo), __uint_as_float(hi));
}

// ---------------------------------------------------------------------------
__global__ void zero_kernel(float* p, int n) {
    int i = blockIdx.x * blockDim.x + threadIdx.x;
    if (i < n) p[i] = 0.f;
}

// ---------------------------------------------------------------------------
// fp32 GEMM with packed f32x2 FMAs: O[b] = A[b] (MxK) * X[b] (KxN), row-major.
// BM=64, BN=128, BK=16, 256 threads, 4x8 per thread (as 4x4 f32x2 pairs).
__global__ void gemm64x128(const float* __restrict__ A, long aBS,
                           const float* __restrict__ X, long xBS,
                           float* __restrict__ O, long oBS,
                           int M, int K, int N)
{
    __shared__ float As[16][64];
    __shared__ float Xs[16][128];
    const int b = blockIdx.z;
    const float* Ab = A + aBS * b;
    const float* Xb = X + xBS * b;
    float* Ob = O + oBS * b;
    const int m0 = blockIdx.y * 64;
    const int n0 = blockIdx.x * 128;
    const int t  = threadIdx.x;
    const int tx = t & 15;    // n-group (8 cols)
    const int ty = t >> 4;    // m-group (4 rows)

    unsigned long long acc[4][4];
#pragma unroll
    for (int i = 0; i < 4; i++)
#pragma unroll
        for (int j = 0; j < 4; j++) acc[i][j] = 0ull;

    const int am = t >> 2;          // 0..63
    const int ak = (t & 3) << 2;    // 0,4,8,12
    const int xk = t >> 5;          // 0..7 (row; +8 for second load)
    const int xc = (t & 31) << 2;   // 0..124

    for (int k0 = 0; k0 < K; k0 += 16) {
        // A tile -> transposed As[k][m]
        float4 av = *(const float4*)&Ab[(long)(m0 + am) * K + k0 + ak];
        As[ak + 0][am] = av.x;
        As[ak + 1][am] = av.y;
        As[ak + 2][am] = av.z;
        As[ak + 3][am] = av.w;
        // X tile: each warp loads one full 128-wide row (conflict-free STS.128)
        *(float4*)&Xs[xk][xc] =
            *(const float4*)&Xb[(long)(k0 + xk) * N + n0 + xc];
        *(float4*)&Xs[xk + 8][xc] =
            *(const float4*)&Xb[(long)(k0 + xk + 8) * N + n0 + xc];
        __syncthreads();
#pragma unroll
        for (int kk = 0; kk < 16; kk++) {
            float4 a = *(const float4*)&As[kk][ty * 4];
            unsigned long long a2[4];
            a2[0] = splat2(a.x); a2[1] = splat2(a.y);
            a2[2] = splat2(a.z); a2[3] = splat2(a.w);
            const ulonglong2* xp = (const ulonglong2*)&Xs[kk][tx * 8];
            ulonglong2 xA = xp[0];
            ulonglong2 xB = xp[1];
            unsigned long long x2[4] = {xA.x, xA.y, xB.x, xB.y};
#pragma unroll
            for (int i = 0; i < 4; i++)
#pragma unroll
                for (int j = 0; j < 4; j++) fma2(acc[i][j], a2[i], x2[j]);
        }
        __syncthreads();
    }
#pragma unroll
    for (int i = 0; i < 4; i++) {
        float o[8];
#pragma unroll
        for (int j = 0; j < 4; j++) {
            float2 v = unpack2(acc[i][j]);
            o[2 * j] = v.x; o[2 * j + 1] = v.y;
        }
        long base = (long)(m0 + ty * 4 + i) * N + n0 + tx * 8;
        *(float4*)&Ob[base]     = make_float4(o[0], o[1], o[2], o[3]);
        *(float4*)&Ob[base + 4] = make_float4(o[4], o[5], o[6], o[7]);
    }
}

// ---------------------------------------------------------------------------
// Depthwise 3x3 conv, dilation 2, zero-pad 2, fused q/k sum-of-squares.
__global__ void dwconv_kernel(const float* __restrict__ in,
                              const float* __restrict__ wdw,
                              float* __restrict__ out,
                              float* __restrict__ sumsq)
{
    const int x  = threadIdx.x;   // 0..127
    const int y  = blockIdx.x;    // 0..127
    const int ch = blockIdx.y;    // 0..575
    const int b  = blockIdx.z;    // 0..7
    const float* ip = in + ((long)b * C3 + ch) * HW;
    const float* wp = wdw + ch * 9;
    float w[9];
#pragma unroll
    for (int i = 0; i < 9; i++) w[i] = __ldg(&wp[i]);

    float acc = 0.f;
#pragma unroll
    for (int i = 0; i < 3; i++) {
        int yy = y + 2 * (i - 1);
        if (yy < 0 || yy >= 128) continue;
#pragma unroll
        for (int j = 0; j < 3; j++) {
            int xx = x + 2 * (j - 1);
            if (xx < 0 || xx >= 128) continue;
            acc += w[i * 3 + j] * ip[yy * 128 + xx];
        }
    }
    out[((long)b * C3 + ch) * HW + y * 128 + x] = acc;

    if (ch < 384) {
        float v = acc * acc;
#pragma unroll
        for (int off = 16; off; off >>= 1) v += __shfl_down_sync(0xffffffffu, v, off);
        __shared__ float ws[4];
        int lane = x & 31, warp = x >> 5;
        if (lane == 0) ws[warp] = v;
        __syncthreads();
        if (x == 0) atomicAdd(&sumsq[b * 384 + ch], ws[0] + ws[1] + ws[2] + ws[3]);
    }
}

// ---------------------------------------------------------------------------
// Raw S = q . k^T (24x24 per (b,head)), split-K over QKCH chunks.
// 2x2 register tile per thread, f32x2 packed inner loop.
// Row stride 130 (even) => every row base is 8B-aligned, packed pairs line up.
#define QKS 130
__global__ void qk_kernel(const float* __restrict__ qkv, float* __restrict__ Spart)
{
    const int chunk = blockIdx.x;  // 0..QKCH-1
    const int bh    = blockIdx.y;  // 0..63
    const int b = bh >> 3, h = bh & 7;
    const float* qp = qkv + ((long)b * C3 + h * 24) * HW;
    const float* kp = qkv + ((long)b * C3 + 192 + h * 24) * HW;
    __shared__ float qs[24 * QKS];
    __shared__ float ks[24 * QKS];
    const int t = threadIdx.x;  // 256
    unsigned long long a00 = 0ull, a01 = 0ull, a10 = 0ull, a11 = 0ull;
    const int cc = (t / 12) * 2;
    const int dd = (t % 12) * 2;
    int n0 = chunk * (HW / QKCH);
    const int iters = (HW / QKCH) / 128;
    for (int it = 0; it < iters; it++, n0 += 128) {
        for (int idx = t; idx < 3072; idx += 256) {
            int r = idx >> 7, ci = idx & 127;
            qs[r * QKS + ci] = qp[(long)r * HW + n0 + ci];
            ks[r * QKS + ci] = kp[(long)r * HW + n0 + ci];
        }
        __syncthreads();
        if (t < 144) {
            // even row stride => all row bases 8B-aligned, no element shift
            const unsigned long long* q0p = (const unsigned long long*)&qs[cc * QKS];
            const unsigned long long* q1p = (const unsigned long long*)&qs[(cc + 1) * QKS];
            const unsigned long long* k0p = (const unsigned long long*)&ks[dd * QKS];
            const unsigned long long* k1p = (const unsigned long long*)&ks[(dd + 1) * QKS];
#pragma unroll 8
            for (int nn = 0; nn < 64; nn++) {
                unsigned long long q0 = q0p[nn];
                unsigned long long q1 = q1p[nn];
                unsigned long long k0 = k0p[nn];
                unsigned long long k1 = k1p[nn];
                fma2(a00, q0, k0); fma2(a01, q0, k1);
                fma2(a10, q1, k0); fma2(a11, q1, k1);
            }
        }
        __syncthreads();
    }
    if (t < 144) {
        float* sp = Spart + ((long)bh * QKCH + chunk) * 576;
        float2 v;
        v = unpack2(a00); sp[cc * 24 + dd]           = v.x + v.y;
        v = unpack2(a01); sp[cc * 24 + dd + 1]       = v.x + v.y;
        v = unpack2(a10); sp[(cc + 1) * 24 + dd]     = v.x + v.y;
        v = unpack2(a11); sp[(cc + 1) * 24 + dd + 1] = v.x + v.y;
    }
}

// ---------------------------------------------------------------------------
// Per batch: reduce split-K, normalize, softmax, fold w_proj into W2.
__global__ void softmax_fold_kernel(const float* __restrict__ Spart,
                                    const float* __restrict__ sumsq,
                                    const float* __restrict__ temp,
                                    const float* __restrict__ wproj,
                                    float* __restrict__ W2)
{
    const int b = blockIdx.x;
    const int t = threadIdx.x;  // 256
    __shared__ float A[8 * 576];
    __shared__ float nq[192], nk[192];
    for (int i = t; i < 192; i += 256) {
        nq[i] = sqrtf(sumsq[b * 384 + i]) + 1e-6f;
        nk[i] = sqrtf(sumsq[b * 384 + 192 + i]) + 1e-6f;
    }
    __syncthreads();
    for (int idx = t; idx < 4608; idx += 256) {
        int h = idx / 576, r = idx % 576;
        int c = r / 24, d = r % 24;
        float s = 0.f;
#pragma unroll
        for (int ck = 0; ck < QKCH; ck++)
            s += Spart[(((long)b * 8 + h) * QKCH + ck) * 576 + r];
        A[idx] = s / (nq[h * 24 + c] * nk[h * 24 + d]) * temp[h];
    }
    __syncthreads();
    if (t < 192) {
        int h = t / 24, c = t % 24;
        float* row = &A[h * 576 + c * 24];
        float m = row[0];
        for (int d = 1; d < 24; d++) m = fmaxf(m, row[d]);
        float s = 0.f;
        for (int d = 0; d < 24; d++) { float e = expf(row[d] - m); row[d] = e; s += e; }
        float inv = 1.f / s;
        for (int d = 0; d < 24; d++) row[d] *= inv;
    }
    __syncthreads();
    for (int idx = t; idx < 36864; idx += 256) {
        int o = idx / 192, g = idx % 192;
        int h = g / 24, d = g % 24;
        float s = 0.f;
#pragma unroll
        for (int c = 0; c < 24; c++)
            s += wproj[o * 192 + h * 24 + c] * A[h * 576 + c * 24 + d];
        W2[((long)b * 192 + o) * 192 + g] = s;
    }
}

// ---------------------------------------------------------------------------
extern "C" void kernel_launch(void* const* d_in, const int* in_sizes, int n_in,
                              void* d_out, int out_size)
{
    const float* x      = (const float*)d_in[0];
    const float* w_qkv  = (const float*)d_in[1];
    const float* w_dw   = (const float*)d_in[2];
    const float* w_proj = (const float*)d_in[3];
    const float* temp   = (const float*)d_in[4];
    float* out = (float*)d_out;

    float *qkv_pre, *qkv_post, *sumsq, *Spart, *W2;
    cudaGetSymbolAddress((void**)&qkv_pre,  g_qkv_pre);
    cudaGetSymbolAddress((void**)&qkv_post, g_qkv_post);
    cudaGetSymbolAddress((void**)&sumsq,    g_sumsq);
    cudaGetSymbolAddress((void**)&Spart,    g_Spart);
    cudaGetSymbolAddress((void**)&W2,       g_W2);

    zero_kernel<<<(NB * 384 + 255) / 256, 256>>>(sumsq, NB * 384);

    // K1: qkv = w_qkv @ x   (per batch: [576,192] x [192,16384])
    gemm64x128<<<dim3(HW / 128, C3 / 64, NB), 256>>>(
        w_qkv, 0L, x, (long)CC * HW, qkv_pre, (long)C3 * HW, C3, CC, HW);

    // K2: depthwise 3x3 dil-2 conv + fused q/k sumsq
    dwconv_kernel<<<dim3(128, C3, NB), 128>>>(qkv_pre, w_dw, qkv_post, sumsq);

    // K3: raw S = q.k^T with split-K partials
    qk_kernel<<<dim3(QKCH, 64), 256>>>(qkv_post, Spart);

    // K4: normalize + softmax + fold proj into W2
    softmax_fold_kernel<<<NB, 256>>>(Spart, sumsq, temp, w_proj, W2);

    // K5: out = W2 @ v  (per batch: [192,192] x [192,16384]) — proj fused
    gemm64x128<<<dim3(HW / 128, CC / 64, NB), 256>>>(
        W2, (long)CC * CC, qkv_post + (long)384 * HW, (long)C3 * HW,
        out, (long)CC * HW, CC, CC, HW);
}

// round 4
// speedup vs baseline: 1.7669x; 1.7669x over previous
#include <cuda_runtime.h>
#include <cuda_bf16.h>
#include <math.h>

// b=8, c=192, h=w=128, heads=8, ch=24, hw=16384, 3c=576
#define HW 16384
#define C3 576
#define CC 192
#define NB 8
#define QKCH 16

// Scratch (allocation-free rule: __device__ globals)
__device__ float g_qkv_pre[75497472];      // [8,576,16384]
__device__ float g_qkv_post[75497472];     // [8,576,16384]
__device__ float g_sumsq[8 * 384];
__device__ float g_Spart[64 * QKCH * 576];
__device__ float g_W2[8 * 192 * 192];

// ---------------------------------------------------------------------------
__device__ __forceinline__ void fma2(unsigned long long& acc,
                                     unsigned long long a, unsigned long long b) {
    asm("fma.rn.f32x2 %0, %1, %2, %0;" : "+l"(acc) : "l"(a), "l"(b));
}
__device__ __forceinline__ float2 unpack2(unsigned long long p) {
    unsigned lo, hi;
    asm("mov.b64 {%0, %1}, %2;" : "=r"(lo), "=r"(hi) : "l"(p));
    return make_float2(__uint_as_float(lo), __uint_as_float(hi));
}

// pack two floats' bf16 roundings into one u32 (low = first)
__device__ __forceinline__ unsigned pkhi(float x, float y) {
    __nv_bfloat162 p = __floats2bfloat162_rn(x, y);
    return *(unsigned*)&p;
}
__device__ __forceinline__ unsigned pklo(float x, float y) {
    float rx = x - __bfloat162float(__float2bfloat16_rn(x));
    float ry = y - __bfloat162float(__float2bfloat16_rn(y));
    __nv_bfloat162 p = __floats2bfloat162_rn(rx, ry);
    return *(unsigned*)&p;
}

__device__ __forceinline__ void mma16816(float* c, const unsigned* a,
                                         unsigned b0, unsigned b1) {
    asm("mma.sync.aligned.m16n8k16.row.col.f32.bf16.bf16.f32 "
        "{%0,%1,%2,%3}, {%4,%5,%6,%7}, {%8,%9}, {%0,%1,%2,%3};"
        : "+f"(c[0]), "+f"(c[1]), "+f"(c[2]), "+f"(c[3])
        : "r"(a[0]), "r"(a[1]), "r"(a[2]), "r"(a[3]), "r"(b0), "r"(b1));
}

// ---------------------------------------------------------------------------
__global__ void zero_kernel(float* p, int n) {
    int i = blockIdx.x * blockDim.x + threadIdx.x;
    if (i < n) p[i] = 0.f;
}

// ---------------------------------------------------------------------------
// Tensor-core GEMM with bf16 hi/lo split (fp32-accurate to ~2^-17):
// O[b] = A[b] (MxK, row-major fp32) * X[b] (KxN, row-major fp32).
// BM=64, BN=128, BK=32, 256 threads (8 warps, each 32x32 via 2x4 m16n8k16).
#define ASTR 40    // A smem stride in halves (per m row)
#define BSTR 132   // B smem stride in u32 (per k-pair row)
__global__ __launch_bounds__(256)
void gemm_bf16s(const float* __restrict__ A, long aBS,
                const float* __restrict__ X, long xBS,
                float* __restrict__ O, long oBS,
                int M, int K, int N)
{
    __shared__ __nv_bfloat16 Ah[64 * ASTR], Al[64 * ASTR];
    __shared__ unsigned Bh[16 * BSTR], Bl[16 * BSTR];

    const int b = blockIdx.z;
    const float* Ab = A + aBS * b;
    const float* Xb = X + xBS * b;
    float* Ob = O + oBS * b;
    const int m0 = blockIdx.y * 64;
    const int n0 = blockIdx.x * 128;
    const int t   = threadIdx.x;
    const int wid = t >> 5;
    const int lane = t & 31;
    const int g   = lane >> 2;   // group id (row within fragment)
    const int tig = lane & 3;    // thread in group
    const int warp_m = wid >> 2; // 0..1 -> m offset 32*warp_m
    const int warp_n = wid & 3;  // 0..3 -> n offset 32*warp_n

    float c[2][4][4];
#pragma unroll
    for (int i = 0; i < 2; i++)
#pragma unroll
        for (int j = 0; j < 4; j++)
#pragma unroll
            for (int q = 0; q < 4; q++) c[i][j][q] = 0.f;

    for (int k0 = 0; k0 < K; k0 += 32) {
        // ---- stage A tile (64x32) as bf16 hi/lo ----
#pragma unroll
        for (int j = 0; j < 2; j++) {
            int flat = (j * 256 + t) * 4;          // 0..2044
            int m = flat >> 5, k = flat & 31;
            float4 v = *(const float4*)&Ab[(long)(m0 + m) * K + k0 + k];
            *(unsigned*)&Ah[m * ASTR + k]     = pkhi(v.x, v.y);
            *(unsigned*)&Ah[m * ASTR + k + 2] = pkhi(v.z, v.w);
            *(unsigned*)&Al[m * ASTR + k]     = pklo(v.x, v.y);
            *(unsigned*)&Al[m * ASTR + k + 2] = pklo(v.z, v.w);
        }
        // ---- stage B tile (32x128) as k-pair-packed bf16 hi/lo ----
#pragma unroll
        for (int j = 0; j < 2; j++) {
            int task = j * 256 + t;                // 0..511
            int pr = task >> 5;                    // k-pair row 0..15
            int nc = (task & 31) * 4;
            const float* r0 = &Xb[(long)(k0 + 2 * pr) * N + n0 + nc];
            float4 u = *(const float4*)r0;
            float4 w = *(const float4*)(r0 + N);
            Bh[pr * BSTR + nc + 0] = pkhi(u.x, w.x);
            Bh[pr * BSTR + nc + 1] = pkhi(u.y, w.y);
            Bh[pr * BSTR + nc + 2] = pkhi(u.z, w.z);
            Bh[pr * BSTR + nc + 3] = pkhi(u.w, w.w);
            Bl[pr * BSTR + nc + 0] = pklo(u.x, w.x);
            Bl[pr * BSTR + nc + 1] = pklo(u.y, w.y);
            Bl[pr * BSTR + nc + 2] = pklo(u.z, w.z);
            Bl[pr * BSTR + nc + 3] = pklo(u.w, w.w);
        }
        __syncthreads();

#pragma unroll
        for (int kh = 0; kh < 2; kh++) {
            const int ks = kh * 16;
            unsigned ah[2][4], al[2][4];
#pragma unroll
            for (int mt = 0; mt < 2; mt++) {
                int rb = warp_m * 32 + mt * 16;
                ah[mt][0] = *(const unsigned*)&Ah[(rb + g) * ASTR + ks + 2 * tig];
                ah[mt][1] = *(const unsigned*)&Ah[(rb + g + 8) * ASTR + ks + 2 * tig];
                ah[mt][2] = *(const unsigned*)&Ah[(rb + g) * ASTR + ks + 2 * tig + 8];
                ah[mt][3] = *(const unsigned*)&Ah[(rb + g + 8) * ASTR + ks + 2 * tig + 8];
                al[mt][0] = *(const unsigned*)&Al[(rb + g) * ASTR + ks + 2 * tig];
                al[mt][1] = *(const unsigned*)&Al[(rb + g + 8) * ASTR + ks + 2 * tig];
                al[mt][2] = *(const unsigned*)&Al[(rb + g) * ASTR + ks + 2 * tig + 8];
                al[mt][3] = *(const unsigned*)&Al[(rb + g + 8) * ASTR + ks + 2 * tig + 8];
            }
#pragma unroll
            for (int nt = 0; nt < 4; nt++) {
                int gc = warp_n * 32 + nt * 8 + g;
                unsigned bh0 = Bh[(kh * 8 + tig) * BSTR + gc];
                unsigned bh1 = Bh[(kh * 8 + tig + 4) * BSTR + gc];
                unsigned bl0 = Bl[(kh * 8 + tig) * BSTR + gc];
                unsigned bl1 = Bl[(kh * 8 + tig + 4) * BSTR + gc];
#pragma unroll
                for (int mt = 0; mt < 2; mt++) {
                    mma16816(c[mt][nt], ah[mt], bh0, bh1);  // Ah*Bh
                    mma16816(c[mt][nt], ah[mt], bl0, bl1);  // Ah*Bl
                    mma16816(c[mt][nt], al[mt], bh0, bh1);  // Al*Bh
                }
            }
        }
        __syncthreads();
    }

    // ---- epilogue ----
#pragma unroll
    for (int mt = 0; mt < 2; mt++) {
        int row = m0 + warp_m * 32 + mt * 16 + g;
#pragma unroll
        for (int nt = 0; nt < 4; nt++) {
            int col = n0 + warp_n * 32 + nt * 8 + 2 * tig;
            *(float2*)&Ob[(long)row * N + col] =
                make_float2(c[mt][nt][0], c[mt][nt][1]);
            *(float2*)&Ob[(long)(row + 8) * N + col] =
                make_float2(c[mt][nt][2], c[mt][nt][3]);
        }
    }
}

// ---------------------------------------------------------------------------
// Depthwise 3x3 conv, dilation 2, zero-pad 2, fused q/k sum-of-squares.
__global__ void dwconv_kernel(const float* __restrict__ in,
                              const float* __restrict__ wdw,
                              float* __restrict__ out,
                              float* __restrict__ sumsq)
{
    const int x  = threadIdx.x;
    const int y  = blockIdx.x;
    const int ch = blockIdx.y;
    const int b  = blockIdx.z;
    const float* ip = in + ((long)b * C3 + ch) * HW;
    const float* wp = wdw + ch * 9;
    float w[9];
#pragma unroll
    for (int i = 0; i < 9; i++) w[i] = __ldg(&wp[i]);

    float acc = 0.f;
#pragma unroll
    for (int i = 0; i < 3; i++) {
        int yy = y + 2 * (i - 1);
        if (yy < 0 || yy >= 128) continue;
#pragma unroll
        for (int j = 0; j < 3; j++) {
            int xx = x + 2 * (j - 1);
            if (xx < 0 || xx >= 128) continue;
            acc += w[i * 3 + j] * ip[yy * 128 + xx];
        }
    }
    out[((long)b * C3 + ch) * HW + y * 128 + x] = acc;

    if (ch < 384) {
        float v = acc * acc;
#pragma unroll
        for (int off = 16; off; off >>= 1) v += __shfl_down_sync(0xffffffffu, v, off);
        __shared__ float ws[4];
        int lane = x & 31, warp = x >> 5;
        if (lane == 0) ws[warp] = v;
        __syncthreads();
        if (x == 0) atomicAdd(&sumsq[b * 384 + ch], ws[0] + ws[1] + ws[2] + ws[3]);
    }
}

// ---------------------------------------------------------------------------
// Raw S = q.k^T (24x24 per (b,head)), split-K, f32x2 inner loop, stride 130.
#define QKS 130
__global__ void qk_kernel(const float* __restrict__ qkv, float* __restrict__ Spart)
{
    const int chunk = blockIdx.x;
    const int bh    = blockIdx.y;
    const int b = bh >> 3, h = bh & 7;
    const float* qp = qkv + ((long)b * C3 + h * 24) * HW;
    const float* kp = qkv + ((long)b * C3 + 192 + h * 24) * HW;
    __shared__ float qs[24 * QKS];
    __shared__ float ks[24 * QKS];
    const int t = threadIdx.x;
    unsigned long long a00 = 0ull, a01 = 0ull, a10 = 0ull, a11 = 0ull;
    const int cc = (t / 12) * 2;
    const int dd = (t % 12) * 2;
    int n0 = chunk * (HW / QKCH);
    const int iters = (HW / QKCH) / 128;
    for (int it = 0; it < iters; it++, n0 += 128) {
        for (int idx = t; idx < 3072; idx += 256) {
            int r = idx >> 7, ci = idx & 127;
            qs[r * QKS + ci] = qp[(long)r * HW + n0 + ci];
            ks[r * QKS + ci] = kp[(long)r * HW + n0 + ci];
        }
        __syncthreads();
        if (t < 144) {
            const unsigned long long* q0p = (const unsigned long long*)&qs[cc * QKS];
            const unsigned long long* q1p = (const unsigned long long*)&qs[(cc + 1) * QKS];
            const unsigned long long* k0p = (const unsigned long long*)&ks[dd * QKS];
            const unsigned long long* k1p = (const unsigned long long*)&ks[(dd + 1) * QKS];
#pragma unroll 8
            for (int nn = 0; nn < 64; nn++) {
                unsigned long long q0 = q0p[nn];
                unsigned long long q1 = q1p[nn];
                unsigned long long k0 = k0p[nn];
                unsigned long long k1 = k1p[nn];
                fma2(a00, q0, k0); fma2(a01, q0, k1);
                fma2(a10, q1, k0); fma2(a11, q1, k1);
            }
        }
        __syncthreads();
    }
    if (t < 144) {
        float* sp = Spart + ((long)bh * QKCH + chunk) * 576;
        float2 v;
        v = unpack2(a00); sp[cc * 24 + dd]           = v.x + v.y;
        v = unpack2(a01); sp[cc * 24 + dd + 1]       = v.x + v.y;
        v = unpack2(a10); sp[(cc + 1) * 24 + dd]     = v.x + v.y;
        v = unpack2(a11); sp[(cc + 1) * 24 + dd + 1] = v.x + v.y;
    }
}

// ---------------------------------------------------------------------------
__global__ void softmax_fold_kernel(const float* __restrict__ Spart,
                                    const float* __restrict__ sumsq,
                                    const float* __restrict__ temp,
                                    const float* __restrict__ wproj,
                                    float* __restrict__ W2)
{
    const int b = blockIdx.x;
    const int t = threadIdx.x;
    __shared__ float A[8 * 576];
    __shared__ float nq[192], nk[192];
    for (int i = t; i < 192; i += 256) {
        nq[i] = sqrtf(sumsq[b * 384 + i]) + 1e-6f;
        nk[i] = sqrtf(sumsq[b * 384 + 192 + i]) + 1e-6f;
    }
    __syncthreads();
    for (int idx = t; idx < 4608; idx += 256) {
        int h = idx / 576, r = idx % 576;
        int cidx = r / 24, d = r % 24;
        float s = 0.f;
#pragma unroll
        for (int ck = 0; ck < QKCH; ck++)
            s += Spart[(((long)b * 8 + h) * QKCH + ck) * 576 + r];
        A[idx] = s / (nq[h * 24 + cidx] * nk[h * 24 + d]) * temp[h];
    }
    __syncthreads();
    if (t < 192) {
        int h = t / 24, cidx = t % 24;
        float* row = &A[h * 576 + cidx * 24];
        float m = row[0];
        for (int d = 1; d < 24; d++) m = fmaxf(m, row[d]);
        float s = 0.f;
        for (int d = 0; d < 24; d++) { float e = expf(row[d] - m); row[d] = e; s += e; }
        float inv = 1.f / s;
        for (int d = 0; d < 24; d++) row[d] *= inv;
    }
    __syncthreads();
    for (int idx = t; idx < 36864; idx += 256) {
        int o = idx / 192, gcol = idx % 192;
        int h = gcol / 24, d = gcol % 24;
        float s = 0.f;
#pragma unroll
        for (int cidx = 0; cidx < 24; cidx++)
            s += wproj[o * 192 + h * 24 + cidx] * A[h * 576 + cidx * 24 + d];
        W2[((long)b * 192 + o) * 192 + gcol] = s;
    }
}

// ---------------------------------------------------------------------------
extern "C" void kernel_launch(void* const* d_in, const int* in_sizes, int n_in,
                              void* d_out, int out_size)
{
    const float* x      = (const float*)d_in[0];
    const float* w_qkv  = (const float*)d_in[1];
    const float* w_dw   = (const float*)d_in[2];
    const float* w_proj = (const float*)d_in[3];
    const float* temp   = (const float*)d_in[4];
    float* out = (float*)d_out;

    float *qkv_pre, *qkv_post, *sumsq, *Spart, *W2;
    cudaGetSymbolAddress((void**)&qkv_pre,  g_qkv_pre);
    cudaGetSymbolAddress((void**)&qkv_post, g_qkv_post);
    cudaGetSymbolAddress((void**)&sumsq,    g_sumsq);
    cudaGetSymbolAddress((void**)&Spart,    g_Spart);
    cudaGetSymbolAddress((void**)&W2,       g_W2);

    zero_kernel<<<(NB * 384 + 255) / 256, 256>>>(sumsq, NB * 384);

    // K1: qkv = w_qkv @ x   (per batch: [576,192] x [192,16384]) — tensor cores
    gemm_bf16s<<<dim3(HW / 128, C3 / 64, NB), 256>>>(
        w_qkv, 0L, x, (long)CC * HW, qkv_pre, (long)C3 * HW, C3, CC, HW);

    // K2: depthwise 3x3 dil-2 conv + fused q/k sumsq
    dwconv_kernel<<<dim3(128, C3, NB), 128>>>(qkv_pre, w_dw, qkv_post, sumsq);

    // K3: raw S = q.k^T with split-K partials
    qk_kernel<<<dim3(QKCH, 64), 256>>>(qkv_post, Spart);

    // K4: normalize + softmax + fold proj into W2
    softmax_fold_kernel<<<NB, 256>>>(Spart, sumsq, temp, w_proj, W2);

    // K5: out = W2 @ v  (per batch: [192,192] x [192,16384]) — tensor cores
    gemm_bf16s<<<dim3(HW / 128, CC / 64, NB), 256>>>(
        W2, (long)CC * CC, qkv_post + (long)384 * HW, (long)C3 * HW,
        out, (long)CC * HW, CC, CC, HW);
}

// round 6
// speedup vs baseline: 2.4372x; 1.3794x over previous
#include <cuda_runtime.h>
#include <cuda_fp16.h>
#include <math.h>

// b=8, c=192, h=w=128, heads=8, ch=24, hw=16384, 3c=576
#define HW 16384
#define C3 576
#define CC 192
#define NB 8
#define QKCH 16

// Scratch (allocation-free rule: __device__ globals)
__device__ __half   g_qkv_pre[75497472];   // [8,576,16384] fp16
__device__ __half   g_qkv_post[75497472];  // [8,576,16384] fp16
__device__ unsigned g_xh[12582912];        // [8][96][16384] fp16-pair packed x
__device__ unsigned g_wh[576 * 96];        // packed w_qkv
__device__ unsigned g_W2h[8 * 192 * 96];   // packed folded proj*attn
__device__ float    g_sumsq[8 * 384];
__device__ float    g_Spart[64 * QKCH * 576];

// ---------------------------------------------------------------------------
__device__ __forceinline__ unsigned pkh(float x, float y) {
    __half2 p = __floats2half2_rn(x, y);
    return *(unsigned*)&p;
}
__device__ __forceinline__ void fma2(unsigned long long& acc,
                                     unsigned long long a, unsigned long long b) {
    asm("fma.rn.f32x2 %0, %1, %2, %0;" : "+l"(acc) : "l"(a), "l"(b));
}
__device__ __forceinline__ float2 unpack2(unsigned long long p) {
    unsigned lo, hi;
    asm("mov.b64 {%0, %1}, %2;" : "=r"(lo), "=r"(hi) : "l"(p));
    return make_float2(__uint_as_float(lo), __uint_as_float(hi));
}
__device__ __forceinline__ void mma_f16(float* c, const unsigned* a,
                                        unsigned b0, unsigned b1) {
    asm("mma.sync.aligned.m16n8k16.row.col.f32.f16.f16.f32 "
        "{%0,%1,%2,%3}, {%4,%5,%6,%7}, {%8,%9}, {%0,%1,%2,%3};"
        : "+f"(c[0]), "+f"(c[1]), "+f"(c[2]), "+f"(c[3])
        : "r"(a[0]), "r"(a[1]), "r"(a[2]), "r"(a[3]), "r"(b0), "r"(b1));
}

// ---------------------------------------------------------------------------
__global__ void zero_kernel(float* p, int n) {
    int i = blockIdx.x * blockDim.x + threadIdx.x;
    if (i < n) p[i] = 0.f;
}

// x fp32 [8][192][16384] -> packed u32 [8][96][16384]
__global__ void presplit_x(const float* __restrict__ x, unsigned* __restrict__ xh)
{
    long task = (long)blockIdx.x * 256 + threadIdx.x;
    int n4 = (int)(task & 4095);
    int kp = (int)((task >> 12) % 96);
    int b  = (int)(task / (4096L * 96));
    const float* r0 = x + ((long)b * CC + 2 * kp) * HW + n4 * 4;
    float4 a = *(const float4*)r0;
    float4 c = *(const float4*)(r0 + HW);
    unsigned* o = xh + ((long)b * 96 + kp) * HW + n4 * 4;
    o[0] = pkh(a.x, c.x); o[1] = pkh(a.y, c.y);
    o[2] = pkh(a.z, c.z); o[3] = pkh(a.w, c.w);
}

// w_qkv fp32 [576][192] -> packed u32 [576][96]
__global__ void presplit_w(const float* __restrict__ w, unsigned* __restrict__ wh)
{
    int i = blockIdx.x * 256 + threadIdx.x;
    if (i >= 576 * 96) return;
    int o = i / 96, j = i % 96;
    float2 v = *(const float2*)&w[o * CC + 2 * j];
    wh[i] = pkh(v.x, v.y);
}

// ---------------------------------------------------------------------------
// fp16 tensor-core GEMM: O[b] = A[b] (MxK) * B[b] (KxN).
// A pre-packed u32 [M][K/2]. B: PACKED_B ? u32 [K/2][N] : half [K][N].
// BM=64, BN=128, BK=32, 256 threads, 8 warps each 32x32.
template<bool PACKED_B, bool HALF_OUT>
__global__ __launch_bounds__(256)
void gemm_f16(const unsigned* __restrict__ Apk, long aBS,
              const void* __restrict__ Bv, long bBS,
              void* __restrict__ Ov, long oBS,
              int M, int K, int N)
{
    __shared__ unsigned As[64 * 20];
    __shared__ unsigned Bs[16 * 136];

    const int b = blockIdx.z;
    const unsigned* Ab = Apk + aBS * b;
    const int m0 = blockIdx.y * 64;
    const int n0 = blockIdx.x * 128;
    const int t = threadIdx.x;
    const int wid = t >> 5, lane = t & 31;
    const int g = lane >> 2, tig = lane & 3;
    const int warp_m = wid >> 2, warp_n = wid & 3;

    float c[2][4][4];
#pragma unroll
    for (int i = 0; i < 2; i++)
#pragma unroll
        for (int j = 0; j < 4; j++)
#pragma unroll
            for (int q = 0; q < 4; q++) c[i][j][q] = 0.f;

    const int Kp = K >> 1;
    for (int k0 = 0; k0 < K; k0 += 32) {
        {
            int row = t >> 2, kq = (t & 3) * 4;
            uint4 v = *(const uint4*)&Ab[(long)(m0 + row) * Kp + (k0 >> 1) + kq];
            *(uint4*)&As[row * 20 + kq] = v;
        }
        if (PACKED_B) {
            const unsigned* Bp = (const unsigned*)Bv + bBS * b;
#pragma unroll
            for (int j = 0; j < 2; j++) {
                int gi = j * 256 + t;
                int pr = gi >> 5, nc = (gi & 31) * 4;
                uint4 v = *(const uint4*)&Bp[(long)((k0 >> 1) + pr) * N + n0 + nc];
                *(uint4*)&Bs[pr * 136 + nc] = v;
            }
        } else {
            const __half* Bh = (const __half*)Bv + bBS * b;
#pragma unroll
            for (int j = 0; j < 2; j++) {
                int gi = j * 256 + t;
                int pr = gi >> 5, nc = (gi & 31) * 4;
                const __half* base = Bh + (long)(k0 + 2 * pr) * N + n0 + nc;
                uint2 a = *(const uint2*)base;
                uint2 bb = *(const uint2*)(base + N);
                Bs[pr * 136 + nc + 0] = __byte_perm(a.x, bb.x, 0x5410);
                Bs[pr * 136 + nc + 1] = __byte_perm(a.x, bb.x, 0x7632);
                Bs[pr * 136 + nc + 2] = __byte_perm(a.y, bb.y, 0x5410);
                Bs[pr * 136 + nc + 3] = __byte_perm(a.y, bb.y, 0x7632);
            }
        }
        __syncthreads();

#pragma unroll
        for (int kh = 0; kh < 2; kh++) {
            unsigned a[2][4];
#pragma unroll
            for (int mt = 0; mt < 2; mt++) {
                int rb = warp_m * 32 + mt * 16;
                a[mt][0] = As[(rb + g) * 20 + kh * 8 + tig];
                a[mt][1] = As[(rb + g + 8) * 20 + kh * 8 + tig];
                a[mt][2] = As[(rb + g) * 20 + kh * 8 + tig + 4];
                a[mt][3] = As[(rb + g + 8) * 20 + kh * 8 + tig + 4];
            }
#pragma unroll
            for (int nt = 0; nt < 4; nt++) {
                int gc = warp_n * 32 + nt * 8 + g;
                unsigned b0 = Bs[(kh * 8 + tig) * 136 + gc];
                unsigned b1 = Bs[(kh * 8 + tig + 4) * 136 + gc];
#pragma unroll
                for (int mt = 0; mt < 2; mt++)
                    mma_f16(c[mt][nt], a[mt], b0, b1);
            }
        }
        __syncthreads();
    }

#pragma unroll
    for (int mt = 0; mt < 2; mt++) {
        int row = m0 + warp_m * 32 + mt * 16 + g;
#pragma unroll
        for (int nt = 0; nt < 4; nt++) {
            int col = n0 + warp_n * 32 + nt * 8 + 2 * tig;
            if (HALF_OUT) {
                __half* Oh = (__half*)Ov + oBS * b;
                *(unsigned*)&Oh[(long)row * N + col] = pkh(c[mt][nt][0], c[mt][nt][1]);
                *(unsigned*)&Oh[(long)(row + 8) * N + col] = pkh(c[mt][nt][2], c[mt][nt][3]);
            } else {
                float* Of = (float*)Ov + oBS * b;
                *(float2*)&Of[(long)row * N + col] =
                    make_float2(c[mt][nt][0], c[mt][nt][1]);
                *(float2*)&Of[(long)(row + 8) * N + col] =
                    make_float2(c[mt][nt][2], c[mt][nt][3]);
            }
        }
    }
}

// ---------------------------------------------------------------------------
// Depthwise 3x3 conv (dilation 2, pad 2), fp16 in/out, fp32 math, fused sumsq.
__global__ void dwconv_kernel(const __half* __restrict__ in,
                              const float* __restrict__ wdw,
                              __half* __restrict__ out,
                              float* __restrict__ sumsq)
{
    const int x  = threadIdx.x;
    const int y  = blockIdx.x;
    const int ch = blockIdx.y;
    const int b  = blockIdx.z;
    const __half* ip = in + ((long)b * C3 + ch) * HW;
    const float* wp = wdw + ch * 9;
    float w[9];
#pragma unroll
    for (int i = 0; i < 9; i++) w[i] = __ldg(&wp[i]);

    float acc = 0.f;
#pragma unroll
    for (int i = 0; i < 3; i++) {
        int yy = y + 2 * (i - 1);
        if (yy < 0 || yy >= 128) continue;
#pragma unroll
        for (int j = 0; j < 3; j++) {
            int xx = x + 2 * (j - 1);
            if (xx < 0 || xx >= 128) continue;
            acc += w[i * 3 + j] * __half2float(ip[yy * 128 + xx]);
        }
    }
    out[((long)b * C3 + ch) * HW + y * 128 + x] = __float2half_rn(acc);

    if (ch < 384) {
        float v = acc * acc;
#pragma unroll
        for (int off = 16; off; off >>= 1) v += __shfl_down_sync(0xffffffffu, v, off);
        __shared__ float ws[4];
        int lane = x & 31, warp = x >> 5;
        if (lane == 0) ws[warp] = v;
        __syncthreads();
        if (x == 0) atomicAdd(&sumsq[b * 384 + ch], ws[0] + ws[1] + ws[2] + ws[3]);
    }
}

// ---------------------------------------------------------------------------
// Raw S = q.k^T (24x24 per (b,head)), split-K over QKCH chunks.
// PROVEN scalar f32x2 kernel (rounds 3-4); staging converts fp16 -> fp32.
#define QKS 130
__global__ void qk_kernel(const __half* __restrict__ qkv, float* __restrict__ Spart)
{
    const int chunk = blockIdx.x;
    const int bh    = blockIdx.y;
    const int b = bh >> 3, h = bh & 7;
    const __half* qp = qkv + ((long)b * C3 + h * 24) * HW;
    const __half* kp = qkv + ((long)b * C3 + 192 + h * 24) * HW;
    __shared__ float qs[24 * QKS];
    __shared__ float ks[24 * QKS];
    const int t = threadIdx.x;
    unsigned long long a00 = 0ull, a01 = 0ull, a10 = 0ull, a11 = 0ull;
    const int cc = (t / 12) * 2;
    const int dd = (t % 12) * 2;
    int n0 = chunk * (HW / QKCH);
    const int iters = (HW / QKCH) / 128;
    for (int it = 0; it < iters; it++, n0 += 128) {
        for (int idx = t; idx < 3072; idx += 256) {
            int r = idx >> 7, ci = idx & 127;
            qs[r * QKS + ci] = __half2float(qp[(long)r * HW + n0 + ci]);
            ks[r * QKS + ci] = __half2float(kp[(long)r * HW + n0 + ci]);
        }
        __syncthreads();
        if (t < 144) {
            const unsigned long long* q0p = (const unsigned long long*)&qs[cc * QKS];
            const unsigned long long* q1p = (const unsigned long long*)&qs[(cc + 1) * QKS];
            const unsigned long long* k0p = (const unsigned long long*)&ks[dd * QKS];
            const unsigned long long* k1p = (const unsigned long long*)&ks[(dd + 1) * QKS];
#pragma unroll 8
            for (int nn = 0; nn < 64; nn++) {
                unsigned long long q0 = q0p[nn];
                unsigned long long q1 = q1p[nn];
                unsigned long long k0 = k0p[nn];
                unsigned long long k1 = k1p[nn];
                fma2(a00, q0, k0); fma2(a01, q0, k1);
                fma2(a10, q1, k0); fma2(a11, q1, k1);
            }
        }
        __syncthreads();
    }
    if (t < 144) {
        float* sp = Spart + ((long)bh * QKCH + chunk) * 576;
        float2 v;
        v = unpack2(a00); sp[cc * 24 + dd]           = v.x + v.y;
        v = unpack2(a01); sp[cc * 24 + dd + 1]       = v.x + v.y;
        v = unpack2(a10); sp[(cc + 1) * 24 + dd]     = v.x + v.y;
        v = unpack2(a11); sp[(cc + 1) * 24 + dd + 1] = v.x + v.y;
    }
}

// ---------------------------------------------------------------------------
// Per batch: reduce split-K, normalize, softmax, fold w_proj -> packed fp16 W2.
__global__ void softmax_fold_kernel(const float* __restrict__ Spart,
                                    const float* __restrict__ sumsq,
                                    const float* __restrict__ temp,
                                    const float* __restrict__ wproj,
                                    unsigned* __restrict__ W2h)
{
    const int b = blockIdx.x;
    const int t = threadIdx.x;
    __shared__ float A[8 * 576];
    __shared__ float nq[192], nk[192];
    for (int i = t; i < 192; i += 256) {
        nq[i] = sqrtf(sumsq[b * 384 + i]) + 1e-6f;
        nk[i] = sqrtf(sumsq[b * 384 + 192 + i]) + 1e-6f;
    }
    __syncthreads();
    for (int idx = t; idx < 4608; idx += 256) {
        int h = idx / 576, r = idx % 576;
        int cidx = r / 24, d = r % 24;
        float s = 0.f;
#pragma unroll
        for (int ck = 0; ck < QKCH; ck++)
            s += Spart[(((long)b * 8 + h) * QKCH + ck) * 576 + r];
        A[idx] = s / (nq[h * 24 + cidx] * nk[h * 24 + d]) * temp[h];
    }
    __syncthreads();
    if (t < 192) {
        int h = t / 24, cidx = t % 24;
        float* row = &A[h * 576 + cidx * 24];
        float m = row[0];
        for (int d = 1; d < 24; d++) m = fmaxf(m, row[d]);
        float s = 0.f;
        for (int d = 0; d < 24; d++) { float e = expf(row[d] - m); row[d] = e; s += e; }
        float inv = 1.f / s;
        for (int d = 0; d < 24; d++) row[d] *= inv;
    }
    __syncthreads();
    // W2[o][g=h*24+d] = sum_c wproj[o, h*24+c] * A[h][c][d]; pack g-pairs
    for (int idx = t; idx < 192 * 96; idx += 256) {
        int o = idx / 96, j = idx % 96;
        int g0 = 2 * j;
        int h = g0 / 24, d0 = g0 % 24;
        float s0 = 0.f, s1 = 0.f;
#pragma unroll
        for (int cidx = 0; cidx < 24; cidx++) {
            float wv = wproj[o * CC + h * 24 + cidx];
            s0 += wv * A[h * 576 + cidx * 24 + d0];
            s1 += wv * A[h * 576 + cidx * 24 + d0 + 1];
        }
        W2h[((long)b * CC + o) * 96 + j] = pkh(s0, s1);
    }
}

// ---------------------------------------------------------------------------
extern "C" void kernel_launch(void* const* d_in, const int* in_sizes, int n_in,
                              void* d_out, int out_size)
{
    const float* x      = (const float*)d_in[0];
    const float* w_qkv  = (const float*)d_in[1];
    const float* w_dw   = (const float*)d_in[2];
    const float* w_proj = (const float*)d_in[3];
    const float* temp   = (const float*)d_in[4];
    float* out = (float*)d_out;

    __half *qkv_pre, *qkv_post;
    unsigned *xh, *wh, *W2h;
    float *sumsq, *Spart;
    cudaGetSymbolAddress((void**)&qkv_pre,  g_qkv_pre);
    cudaGetSymbolAddress((void**)&qkv_post, g_qkv_post);
    cudaGetSymbolAddress((void**)&xh,       g_xh);
    cudaGetSymbolAddress((void**)&wh,       g_wh);
    cudaGetSymbolAddress((void**)&W2h,      g_W2h);
    cudaGetSymbolAddress((void**)&sumsq,    g_sumsq);
    cudaGetSymbolAddress((void**)&Spart,    g_Spart);

    zero_kernel<<<(NB * 384 + 255) / 256, 256>>>(sumsq, NB * 384);

    // pre-pack x and w_qkv to fp16 k-pair layout
    presplit_x<<<12288, 256>>>(x, xh);
    presplit_w<<<(576 * 96 + 255) / 256, 256>>>(w_qkv, wh);

    // K1: qkv = w_qkv @ x  -> fp16
    gemm_f16<true, true><<<dim3(HW / 128, C3 / 64, NB), 256>>>(
        wh, 0L, xh, 96L * HW, qkv_pre, (long)C3 * HW, C3, CC, HW);

    // K2: depthwise conv + sumsq
    dwconv_kernel<<<dim3(128, C3, NB), 128>>>(qkv_pre, w_dw, qkv_post, sumsq);

    // K3: scalar f32x2 q.k^T (proven)
    qk_kernel<<<dim3(QKCH, 64), 256>>>(qkv_post, Spart);

    // K4: normalize + softmax + fold -> packed fp16 W2
    softmax_fold_kernel<<<NB, 256>>>(Spart, sumsq, temp, w_proj, W2h);

    // K5: out = W2 @ v  (v = fp16 rows 384.. of qkv_post), fp32 out
    gemm_f16<false, false><<<dim3(HW / 128, CC / 64, NB), 256>>>(
        W2h, (long)CC * 96, qkv_post + 384L * HW, (long)C3 * HW,
        out, (long)CC * HW, CC, CC, HW);
}

// round 7
// speedup vs baseline: 3.9239x; 1.6100x over previous
#include <cuda_runtime.h>
#include <cuda_fp16.h>
#include <math.h>

// b=8, c=192, h=w=128, heads=8, ch=24, hw=16384, 3c=576
#define HW 16384
#define C3 576
#define CC 192
#define NB 8
#define QKCH 16

// Scratch (allocation-free rule: __device__ globals)
__device__ __half   g_qkv_pre[75497472];   // [8,576,16384] fp16
__device__ __half   g_qkv_post[75497472];  // [8,576,16384] fp16
__device__ unsigned g_wh[576 * 96];        // packed w_qkv
__device__ unsigned g_W2h[8 * 192 * 96];   // packed folded proj*attn
__device__ float    g_sumsq[8 * 384];
__device__ float    g_Spart[64 * QKCH * 576];

// ---------------------------------------------------------------------------
__device__ __forceinline__ unsigned pkh(float x, float y) {
    __half2 p = __floats2half2_rn(x, y);
    return *(unsigned*)&p;
}
__device__ __forceinline__ void fma2(unsigned long long& acc,
                                     unsigned long long a, unsigned long long b) {
    asm("fma.rn.f32x2 %0, %1, %2, %0;" : "+l"(acc) : "l"(a), "l"(b));
}
__device__ __forceinline__ float2 unpack2(unsigned long long p) {
    unsigned lo, hi;
    asm("mov.b64 {%0, %1}, %2;" : "=r"(lo), "=r"(hi) : "l"(p));
    return make_float2(__uint_as_float(lo), __uint_as_float(hi));
}
__device__ __forceinline__ void mma_f16(float* c, const unsigned* a,
                                        unsigned b0, unsigned b1) {
    asm("mma.sync.aligned.m16n8k16.row.col.f32.f16.f16.f32 "
        "{%0,%1,%2,%3}, {%4,%5,%6,%7}, {%8,%9}, {%0,%1,%2,%3};"
        : "+f"(c[0]), "+f"(c[1]), "+f"(c[2]), "+f"(c[3])
        : "r"(a[0]), "r"(a[1]), "r"(a[2]), "r"(a[3]), "r"(b0), "r"(b1));
}

// ---------------------------------------------------------------------------
// w_qkv fp32 [576][192] -> packed u32 [576][96]
__global__ void presplit_w(const float* __restrict__ w, unsigned* __restrict__ wh)
{
    int i = blockIdx.x * 256 + threadIdx.x;
    if (i >= 576 * 96) return;
    int o = i / 96, j = i % 96;
    float2 v = *(const float2*)&w[o * CC + 2 * j];
    wh[i] = pkh(v.x, v.y);
}

// ---------------------------------------------------------------------------
// fp16 tensor-core GEMM: O[b] = A[b] (MxK) * B[b] (KxN).
// A pre-packed u32 [M][K/2].
// BMODE: 0 = B packed u32 [K/2][N], 1 = B half [K][N], 2 = B float [K][N].
// BM=64, BN=128, BK=32, 256 threads, 8 warps each 32x32.
template<int BMODE, bool HALF_OUT>
__global__ __launch_bounds__(256)
void gemm_f16(const unsigned* __restrict__ Apk, long aBS,
              const void* __restrict__ Bv, long bBS,
              void* __restrict__ Ov, long oBS,
              int M, int K, int N)
{
    __shared__ unsigned As[64 * 20];
    __shared__ unsigned Bs[16 * 136];

    const int b = blockIdx.z;
    const unsigned* Ab = Apk + aBS * b;
    const int m0 = blockIdx.y * 64;
    const int n0 = blockIdx.x * 128;
    const int t = threadIdx.x;
    const int wid = t >> 5, lane = t & 31;
    const int g = lane >> 2, tig = lane & 3;
    const int warp_m = wid >> 2, warp_n = wid & 3;

    float c[2][4][4];
#pragma unroll
    for (int i = 0; i < 2; i++)
#pragma unroll
        for (int j = 0; j < 4; j++)
#pragma unroll
            for (int q = 0; q < 4; q++) c[i][j][q] = 0.f;

    const int Kp = K >> 1;
    for (int k0 = 0; k0 < K; k0 += 32) {
        {
            int row = t >> 2, kq = (t & 3) * 4;
            uint4 v = *(const uint4*)&Ab[(long)(m0 + row) * Kp + (k0 >> 1) + kq];
            *(uint4*)&As[row * 20 + kq] = v;
        }
        if (BMODE == 0) {
            const unsigned* Bp = (const unsigned*)Bv + bBS * b;
#pragma unroll
            for (int j = 0; j < 2; j++) {
                int gi = j * 256 + t;
                int pr = gi >> 5, nc = (gi & 31) * 4;
                uint4 v = *(const uint4*)&Bp[(long)((k0 >> 1) + pr) * N + n0 + nc];
                *(uint4*)&Bs[pr * 136 + nc] = v;
            }
        } else if (BMODE == 1) {
            const __half* Bh = (const __half*)Bv + bBS * b;
#pragma unroll
            for (int j = 0; j < 2; j++) {
                int gi = j * 256 + t;
                int pr = gi >> 5, nc = (gi & 31) * 4;
                const __half* base = Bh + (long)(k0 + 2 * pr) * N + n0 + nc;
                uint2 a = *(const uint2*)base;
                uint2 bb = *(const uint2*)(base + N);
                Bs[pr * 136 + nc + 0] = __byte_perm(a.x, bb.x, 0x5410);
                Bs[pr * 136 + nc + 1] = __byte_perm(a.x, bb.x, 0x7632);
                Bs[pr * 136 + nc + 2] = __byte_perm(a.y, bb.y, 0x5410);
                Bs[pr * 136 + nc + 3] = __byte_perm(a.y, bb.y, 0x7632);
            }
        } else {
            const float* Bf = (const float*)Bv + bBS * b;
#pragma unroll
            for (int j = 0; j < 2; j++) {
                int gi = j * 256 + t;
                int pr = gi >> 5, nc = (gi & 31) * 4;
                const float* base = Bf + (long)(k0 + 2 * pr) * N + n0 + nc;
                float4 u = *(const float4*)base;
                float4 v = *(const float4*)(base + N);
                Bs[pr * 136 + nc + 0] = pkh(u.x, v.x);
                Bs[pr * 136 + nc + 1] = pkh(u.y, v.y);
                Bs[pr * 136 + nc + 2] = pkh(u.z, v.z);
                Bs[pr * 136 + nc + 3] = pkh(u.w, v.w);
            }
        }
        __syncthreads();

#pragma unroll
        for (int kh = 0; kh < 2; kh++) {
            unsigned a[2][4];
#pragma unroll
            for (int mt = 0; mt < 2; mt++) {
                int rb = warp_m * 32 + mt * 16;
                a[mt][0] = As[(rb + g) * 20 + kh * 8 + tig];
                a[mt][1] = As[(rb + g + 8) * 20 + kh * 8 + tig];
                a[mt][2] = As[(rb + g) * 20 + kh * 8 + tig + 4];
                a[mt][3] = As[(rb + g + 8) * 20 + kh * 8 + tig + 4];
            }
#pragma unroll
            for (int nt = 0; nt < 4; nt++) {
                int gc = warp_n * 32 + nt * 8 + g;
                unsigned b0 = Bs[(kh * 8 + tig) * 136 + gc];
                unsigned b1 = Bs[(kh * 8 + tig + 4) * 136 + gc];
#pragma unroll
                for (int mt = 0; mt < 2; mt++)
                    mma_f16(c[mt][nt], a[mt], b0, b1);
            }
        }
        __syncthreads();
    }

#pragma unroll
    for (int mt = 0; mt < 2; mt++) {
        int row = m0 + warp_m * 32 + mt * 16 + g;
#pragma unroll
        for (int nt = 0; nt < 4; nt++) {
            int col = n0 + warp_n * 32 + nt * 8 + 2 * tig;
            if (HALF_OUT) {
                __half* Oh = (__half*)Ov + oBS * b;
                *(unsigned*)&Oh[(long)row * N + col] = pkh(c[mt][nt][0], c[mt][nt][1]);
                *(unsigned*)&Oh[(long)(row + 8) * N + col] = pkh(c[mt][nt][2], c[mt][nt][3]);
            } else {
                float* Of = (float*)Ov + oBS * b;
                *(float2*)&Of[(long)row * N + col] =
                    make_float2(c[mt][nt][0], c[mt][nt][1]);
                *(float2*)&Of[(long)(row + 8) * N + col] =
                    make_float2(c[mt][nt][2], c[mt][nt][3]);
            }
        }
    }
}

// ---------------------------------------------------------------------------
// Depthwise 3x3 conv (dilation 2, pad 2): one block per (ch, b) plane.
// Whole 128x128 fp16 plane staged in SMEM (read once), 2 pixels/thread/iter
// via half2 taps, fp32 math, fused block-reduced sumsq (no atomics).
__global__ __launch_bounds__(256)
void dwconv_plane(const __half* __restrict__ in,
                  const float* __restrict__ wdw,
                  __half* __restrict__ out,
                  float* __restrict__ sumsq)
{
    __shared__ __half sp[16384];
    __shared__ float wred[8];
    const int ch = blockIdx.x;   // 0..575
    const int b  = blockIdx.y;   // 0..7
    const int t  = threadIdx.x;  // 256
    const __half* ip = in + ((long)b * C3 + ch) * HW;

    // stage full plane: 8 x uint4 per thread (coalesced, 16B)
#pragma unroll
    for (int i = 0; i < 8; i++) {
        int off = (i * 256 + t) * 8;
        *(uint4*)&sp[off] = *(const uint4*)&ip[off];
    }
    float w[9];
#pragma unroll
    for (int i = 0; i < 9; i++) w[i] = __ldg(&wdw[ch * 9 + i]);
    __syncthreads();

    const __half2* sp2 = (const __half2*)sp;
    unsigned* op = (unsigned*)(out + ((long)b * C3 + ch) * HW);
    float ss = 0.f;

#pragma unroll 4
    for (int i = 0; i < 32; i++) {
        int p = i * 512 + t * 2;        // even pixel index
        int y = p >> 7, x = p & 127;    // x even
        float a0 = 0.f, a1 = 0.f;
#pragma unroll
        for (int r = 0; r < 3; r++) {
            int yy = y + 2 * (r - 1);
            if (yy < 0 || yy >= 128) continue;
            int ro = yy * 64;  // row offset in half2 units
            float2 p0 = (x >= 2)
                ? __half22float2(sp2[ro + ((x - 2) >> 1)]) : make_float2(0.f, 0.f);
            float2 p1 = __half22float2(sp2[ro + (x >> 1)]);
            float2 p2 = (x <= 124)
                ? __half22float2(sp2[ro + ((x + 2) >> 1)]) : make_float2(0.f, 0.f);
            float w0 = w[r * 3 + 0], w1 = w[r * 3 + 1], w2 = w[r * 3 + 2];
            a0 += w0 * p0.x + w1 * p1.x + w2 * p2.x;
            a1 += w0 * p0.y + w1 * p1.y + w2 * p2.y;
        }
        op[p >> 1] = pkh(a0, a1);
        ss += a0 * a0 + a1 * a1;
    }

    if (ch < 384) {
#pragma unroll
        for (int off = 16; off; off >>= 1)
            ss += __shfl_down_sync(0xffffffffu, ss, off);
        if ((t & 31) == 0) wred[t >> 5] = ss;
        __syncthreads();
        if (t == 0) {
            float s = 0.f;
#pragma unroll
            for (int i = 0; i < 8; i++) s += wred[i];
            sumsq[b * 384 + ch] = s;
        }
    }
}

// ---------------------------------------------------------------------------
// Raw S = q.k^T (24x24 per (b,head)), split-K over QKCH chunks.
// Proven scalar f32x2 kernel; staging converts fp16 -> fp32.
#define QKS 130
__global__ void qk_kernel(const __half* __restrict__ qkv, float* __restrict__ Spart)
{
    const int chunk = blockIdx.x;
    const int bh    = blockIdx.y;
    const int b = bh >> 3, h = bh & 7;
    const __half* qp = qkv + ((long)b * C3 + h * 24) * HW;
    const __half* kp = qkv + ((long)b * C3 + 192 + h * 24) * HW;
    __shared__ float qs[24 * QKS];
    __shared__ float ks[24 * QKS];
    const int t = threadIdx.x;
    unsigned long long a00 = 0ull, a01 = 0ull, a10 = 0ull, a11 = 0ull;
    const int cc = (t / 12) * 2;
    const int dd = (t % 12) * 2;
    int n0 = chunk * (HW / QKCH);
    const int iters = (HW / QKCH) / 128;
    for (int it = 0; it < iters; it++, n0 += 128) {
        for (int idx = t; idx < 3072; idx += 256) {
            int r = idx >> 7, ci = idx & 127;
            qs[r * QKS + ci] = __half2float(qp[(long)r * HW + n0 + ci]);
            ks[r * QKS + ci] = __half2float(kp[(long)r * HW + n0 + ci]);
        }
        __syncthreads();
        if (t < 144) {
            const unsigned long long* q0p = (const unsigned long long*)&qs[cc * QKS];
            const unsigned long long* q1p = (const unsigned long long*)&qs[(cc + 1) * QKS];
            const unsigned long long* k0p = (const unsigned long long*)&ks[dd * QKS];
            const unsigned long long* k1p = (const unsigned long long*)&ks[(dd + 1) * QKS];
#pragma unroll 8
            for (int nn = 0; nn < 64; nn++) {
                unsigned long long q0 = q0p[nn];
                unsigned long long q1 = q1p[nn];
                unsigned long long k0 = k0p[nn];
                unsigned long long k1 = k1p[nn];
                fma2(a00, q0, k0); fma2(a01, q0, k1);
                fma2(a10, q1, k0); fma2(a11, q1, k1);
            }
        }
        __syncthreads();
    }
    if (t < 144) {
        float* sp = Spart + ((long)bh * QKCH + chunk) * 576;
        float2 v;
        v = unpack2(a00); sp[cc * 24 + dd]           = v.x + v.y;
        v = unpack2(a01); sp[cc * 24 + dd + 1]       = v.x + v.y;
        v = unpack2(a10); sp[(cc + 1) * 24 + dd]     = v.x + v.y;
        v = unpack2(a11); sp[(cc + 1) * 24 + dd + 1] = v.x + v.y;
    }
}

// ---------------------------------------------------------------------------
// Per batch: reduce split-K, normalize, softmax, fold w_proj -> packed fp16 W2.
__global__ void softmax_fold_kernel(const float* __restrict__ Spart,
                                    const float* __restrict__ sumsq,
                                    const float* __restrict__ temp,
                                    const float* __restrict__ wproj,
                                    unsigned* __restrict__ W2h)
{
    const int b = blockIdx.x;
    const int t = threadIdx.x;
    __shared__ float A[8 * 576];
    __shared__ float nq[192], nk[192];
    for (int i = t; i < 192; i += 256) {
        nq[i] = sqrtf(sumsq[b * 384 + i]) + 1e-6f;
        nk[i] = sqrtf(sumsq[b * 384 + 192 + i]) + 1e-6f;
    }
    __syncthreads();
    for (int idx = t; idx < 4608; idx += 256) {
        int h = idx / 576, r = idx % 576;
        int cidx = r / 24, d = r % 24;
        float s = 0.f;
#pragma unroll
        for (int ck = 0; ck < QKCH; ck++)
            s += Spart[(((long)b * 8 + h) * QKCH + ck) * 576 + r];
        A[idx] = s / (nq[h * 24 + cidx] * nk[h * 24 + d]) * temp[h];
    }
    __syncthreads();
    if (t < 192) {
        int h = t / 24, cidx = t % 24;
        float* row = &A[h * 576 + cidx * 24];
        float m = row[0];
        for (int d = 1; d < 24; d++) m = fmaxf(m, row[d]);
        float s = 0.f;
        for (int d = 0; d < 24; d++) { float e = expf(row[d] - m); row[d] = e; s += e; }
        float inv = 1.f / s;
        for (int d = 0; d < 24; d++) row[d] *= inv;
    }
    __syncthreads();
    for (int idx = t; idx < 192 * 96; idx += 256) {
        int o = idx / 96, j = idx % 96;
        int g0 = 2 * j;
        int h = g0 / 24, d0 = g0 % 24;
        float s0 = 0.f, s1 = 0.f;
#pragma unroll
        for (int cidx = 0; cidx < 24; cidx++) {
            float wv = wproj[o * CC + h * 24 + cidx];
            s0 += wv * A[h * 576 + cidx * 24 + d0];
            s1 += wv * A[h * 576 + cidx * 24 + d0 + 1];
        }
        W2h[((long)b * CC + o) * 96 + j] = pkh(s0, s1);
    }
}

// ---------------------------------------------------------------------------
extern "C" void kernel_launch(void* const* d_in, const int* in_sizes, int n_in,
                              void* d_out, int out_size)
{
    const float* x      = (const float*)d_in[0];
    const float* w_qkv  = (const float*)d_in[1];
    const float* w_dw   = (const float*)d_in[2];
    const float* w_proj = (const float*)d_in[3];
    const float* temp   = (const float*)d_in[4];
    float* out = (float*)d_out;

    __half *qkv_pre, *qkv_post;
    unsigned *wh, *W2h;
    float *sumsq, *Spart;
    cudaGetSymbolAddress((void**)&qkv_pre,  g_qkv_pre);
    cudaGetSymbolAddress((void**)&qkv_post, g_qkv_post);
    cudaGetSymbolAddress((void**)&wh,       g_wh);
    cudaGetSymbolAddress((void**)&W2h,      g_W2h);
    cudaGetSymbolAddress((void**)&sumsq,    g_sumsq);
    cudaGetSymbolAddress((void**)&Spart,    g_Spart);

    // pack w_qkv to fp16 k-pair layout (tiny)
    presplit_w<<<(576 * 96 + 255) / 256, 256>>>(w_qkv, wh);

    // K1: qkv = w_qkv @ x  -> fp16 (B = fp32 x, converted during staging)
    gemm_f16<2, true><<<dim3(HW / 128, C3 / 64, NB), 256>>>(
        wh, 0L, x, (long)CC * HW, qkv_pre, (long)C3 * HW, C3, CC, HW);

    // K2: depthwise conv (plane-in-smem) + block-reduced sumsq
    dwconv_plane<<<dim3(C3, NB), 256>>>(qkv_pre, w_dw, qkv_post, sumsq);

    // K3: scalar f32x2 q.k^T (proven)
    qk_kernel<<<dim3(QKCH, 64), 256>>>(qkv_post, Spart);

    // K4: normalize + softmax + fold -> packed fp16 W2
    softmax_fold_kernel<<<NB, 256>>>(Spart, sumsq, temp, w_proj, W2h);

    // K5: out = W2 @ v  (v = fp16 rows 384.. of qkv_post), fp32 out
    gemm_f16<1, false><<<dim3(HW / 128, CC / 64, NB), 256>>>(
        W2h, (long)CC * 96, qkv_post + 384L * HW, (long)C3 * HW,
        out, (long)CC * HW, CC, CC, HW);
}

// round 8
// speedup vs baseline: 4.0565x; 1.0338x over previous
#include <cuda_runtime.h>
#include <cuda_fp16.h>
#include <math.h>

// b=8, c=192, h=w=128, heads=8, ch=24, hw=16384, 3c=576
#define HW 16384
#define C3 576
#define CC 192
#define NB 8
#define QKCH 16

// Scratch (allocation-free rule: __device__ globals)
__device__ __half   g_qkv_pre[75497472];   // [8,576,16384] fp16
__device__ __half   g_qkv_post[75497472];  // [8,576,16384] fp16
__device__ unsigned g_wh[576 * 96];        // packed w_qkv
__device__ unsigned g_W2h[8 * 192 * 96];   // packed folded proj*attn
__device__ float    g_sumsq[8 * 384];
__device__ float    g_Spart[64 * QKCH * 576];

// ---------------------------------------------------------------------------
__device__ __forceinline__ unsigned pkh(float x, float y) {
    __half2 p = __floats2half2_rn(x, y);
    return *(unsigned*)&p;
}
__device__ __forceinline__ void fma2(unsigned long long& acc,
                                     unsigned long long a, unsigned long long b) {
    asm("fma.rn.f32x2 %0, %1, %2, %0;" : "+l"(acc) : "l"(a), "l"(b));
}
__device__ __forceinline__ float2 unpack2(unsigned long long p) {
    unsigned lo, hi;
    asm("mov.b64 {%0, %1}, %2;" : "=r"(lo), "=r"(hi) : "l"(p));
    return make_float2(__uint_as_float(lo), __uint_as_float(hi));
}
__device__ __forceinline__ void mma_f16(float* c, const unsigned* a,
                                        unsigned b0, unsigned b1) {
    asm("mma.sync.aligned.m16n8k16.row.col.f32.f16.f16.f32 "
        "{%0,%1,%2,%3}, {%4,%5,%6,%7}, {%8,%9}, {%0,%1,%2,%3};"
        : "+f"(c[0]), "+f"(c[1]), "+f"(c[2]), "+f"(c[3])
        : "r"(a[0]), "r"(a[1]), "r"(a[2]), "r"(a[3]), "r"(b0), "r"(b1));
}

// ---------------------------------------------------------------------------
// w_qkv fp32 [576][192] -> packed u32 [576][96]
__global__ void presplit_w(const float* __restrict__ w, unsigned* __restrict__ wh)
{
    int i = blockIdx.x * 256 + threadIdx.x;
    if (i >= 576 * 96) return;
    int o = i / 96, j = i % 96;
    float2 v = *(const float2*)&w[o * CC + 2 * j];
    wh[i] = pkh(v.x, v.y);
}

// ---------------------------------------------------------------------------
// B-resident fp16 tensor-core GEMM. K fixed = 192.
// One block owns (n-tile of 128, batch); stages the FULL B tile (96 k-pairs x
// 128 n, packed u32) once in dynamic SMEM, then loops over all M/64 m-tiles.
// BMODE: 1 = B half [K][N], 2 = B float [K][N]. A pre-packed u32 [M][96].
#define BST 132   // Bs row stride (u32)
#define AST 100   // As row stride (u32)
__global__ __launch_bounds__(256)
void gemm_nres(const unsigned* __restrict__ Apk, long aBS,
               const void* __restrict__ Bv, long bBS,
               void* __restrict__ Ov, long oBS,
               int M, int N, int BMODE, int HALF_OUT)
{
    extern __shared__ unsigned sh[];
    unsigned* Bs = sh;                 // [96][BST]
    unsigned* As = sh + 96 * BST;      // [64][AST]

    const int b = blockIdx.y;
    const int n0 = blockIdx.x * 128;
    const unsigned* Ab = Apk + aBS * b;
    const int t = threadIdx.x;
    const int wid = t >> 5, lane = t & 31;
    const int g = lane >> 2, tig = lane & 3;
    const int warp_m = wid >> 2, warp_n = wid & 3;

    // ---- stage full B tile (192 k x 128 n) as packed u32 k-pairs ----
    if (BMODE == 2) {
        const float* Bf = (const float*)Bv + bBS * b;
#pragma unroll
        for (int j = 0; j < 12; j++) {
            int gi = j * 256 + t;           // 0..3071
            int pr = gi >> 5;               // 0..95
            int nc = (gi & 31) * 4;
            const float* base = Bf + (long)(2 * pr) * N + n0 + nc;
            float4 u = *(const float4*)base;
            float4 v = *(const float4*)(base + N);
            Bs[pr * BST + nc + 0] = pkh(u.x, v.x);
            Bs[pr * BST + nc + 1] = pkh(u.y, v.y);
            Bs[pr * BST + nc + 2] = pkh(u.z, v.z);
            Bs[pr * BST + nc + 3] = pkh(u.w, v.w);
        }
    } else {
        const __half* Bh = (const __half*)Bv + bBS * b;
#pragma unroll
        for (int j = 0; j < 12; j++) {
            int gi = j * 256 + t;
            int pr = gi >> 5;
            int nc = (gi & 31) * 4;
            const __half* base = Bh + (long)(2 * pr) * N + n0 + nc;
            uint2 a = *(const uint2*)base;
            uint2 bb = *(const uint2*)(base + N);
            Bs[pr * BST + nc + 0] = __byte_perm(a.x, bb.x, 0x5410);
            Bs[pr * BST + nc + 1] = __byte_perm(a.x, bb.x, 0x7632);
            Bs[pr * BST + nc + 2] = __byte_perm(a.y, bb.y, 0x5410);
            Bs[pr * BST + nc + 3] = __byte_perm(a.y, bb.y, 0x7632);
        }
    }
    __syncthreads();

    const int mtiles = M / 64;
    for (int mt = 0; mt < mtiles; mt++) {
        const int m0 = mt * 64;
        // stage A m-tile: 64 rows x 96 u32
#pragma unroll
        for (int j = 0; j < 6; j++) {
            int gi = j * 256 + t;           // 0..1535
            int row = gi / 24;
            int kq = (gi % 24) * 4;
            uint4 v = *(const uint4*)&Ab[(long)(m0 + row) * 96 + kq];
            *(uint4*)&As[row * AST + kq] = v;
        }
        __syncthreads();

        float c[2][4][4];
#pragma unroll
        for (int i = 0; i < 2; i++)
#pragma unroll
            for (int j = 0; j < 4; j++)
#pragma unroll
                for (int q = 0; q < 4; q++) c[i][j][q] = 0.f;

        // mainloop over resident SMEM: 12 mma steps of k=16, no syncs
#pragma unroll
        for (int kp0 = 0; kp0 < 96; kp0 += 8) {
            unsigned a[2][4];
#pragma unroll
            for (int m2 = 0; m2 < 2; m2++) {
                int rb = warp_m * 32 + m2 * 16;
                a[m2][0] = As[(rb + g) * AST + kp0 + tig];
                a[m2][1] = As[(rb + g + 8) * AST + kp0 + tig];
                a[m2][2] = As[(rb + g) * AST + kp0 + tig + 4];
                a[m2][3] = As[(rb + g + 8) * AST + kp0 + tig + 4];
            }
#pragma unroll
            for (int nt = 0; nt < 4; nt++) {
                int gc = warp_n * 32 + nt * 8 + g;
                unsigned b0 = Bs[(kp0 + tig) * BST + gc];
                unsigned b1 = Bs[(kp0 + tig + 4) * BST + gc];
#pragma unroll
                for (int m2 = 0; m2 < 2; m2++)
                    mma_f16(c[m2][nt], a[m2], b0, b1);
            }
        }

        // epilogue
#pragma unroll
        for (int m2 = 0; m2 < 2; m2++) {
            int row = m0 + warp_m * 32 + m2 * 16 + g;
#pragma unroll
            for (int nt = 0; nt < 4; nt++) {
                int col = n0 + warp_n * 32 + nt * 8 + 2 * tig;
                if (HALF_OUT) {
                    __half* Oh = (__half*)Ov + oBS * b;
                    *(unsigned*)&Oh[(long)row * N + col] =
                        pkh(c[m2][nt][0], c[m2][nt][1]);
                    *(unsigned*)&Oh[(long)(row + 8) * N + col] =
                        pkh(c[m2][nt][2], c[m2][nt][3]);
                } else {
                    float* Of = (float*)Ov + oBS * b;
                    *(float2*)&Of[(long)row * N + col] =
                        make_float2(c[m2][nt][0], c[m2][nt][1]);
                    *(float2*)&Of[(long)(row + 8) * N + col] =
                        make_float2(c[m2][nt][2], c[m2][nt][3]);
                }
            }
        }
        __syncthreads();
    }
}

// ---------------------------------------------------------------------------
// Depthwise 3x3 conv (dilation 2, pad 2): one block per (ch, b) plane.
__global__ __launch_bounds__(256)
void dwconv_plane(const __half* __restrict__ in,
                  const float* __restrict__ wdw,
                  __half* __restrict__ out,
                  float* __restrict__ sumsq)
{
    __shared__ __half sp[16384];
    __shared__ float wred[8];
    const int ch = blockIdx.x;
    const int b  = blockIdx.y;
    const int t  = threadIdx.x;
    const __half* ip = in + ((long)b * C3 + ch) * HW;

#pragma unroll
    for (int i = 0; i < 8; i++) {
        int off = (i * 256 + t) * 8;
        *(uint4*)&sp[off] = *(const uint4*)&ip[off];
    }
    float w[9];
#pragma unroll
    for (int i = 0; i < 9; i++) w[i] = __ldg(&wdw[ch * 9 + i]);
    __syncthreads();

    const __half2* sp2 = (const __half2*)sp;
    unsigned* op = (unsigned*)(out + ((long)b * C3 + ch) * HW);
    float ss = 0.f;

#pragma unroll 4
    for (int i = 0; i < 32; i++) {
        int p = i * 512 + t * 2;
        int y = p >> 7, x = p & 127;
        float a0 = 0.f, a1 = 0.f;
#pragma unroll
        for (int r = 0; r < 3; r++) {
            int yy = y + 2 * (r - 1);
            if (yy < 0 || yy >= 128) continue;
            int ro = yy * 64;
            float2 p0 = (x >= 2)
                ? __half22float2(sp2[ro + ((x - 2) >> 1)]) : make_float2(0.f, 0.f);
            float2 p1 = __half22float2(sp2[ro + (x >> 1)]);
            float2 p2 = (x <= 124)
                ? __half22float2(sp2[ro + ((x + 2) >> 1)]) : make_float2(0.f, 0.f);
            float w0 = w[r * 3 + 0], w1 = w[r * 3 + 1], w2 = w[r * 3 + 2];
            a0 += w0 * p0.x + w1 * p1.x + w2 * p2.x;
            a1 += w0 * p0.y + w1 * p1.y + w2 * p2.y;
        }
        op[p >> 1] = pkh(a0, a1);
        ss += a0 * a0 + a1 * a1;
    }

    if (ch < 384) {
#pragma unroll
        for (int off = 16; off; off >>= 1)
            ss += __shfl_down_sync(0xffffffffu, ss, off);
        if ((t & 31) == 0) wred[t >> 5] = ss;
        __syncthreads();
        if (t == 0) {
            float s = 0.f;
#pragma unroll
            for (int i = 0; i < 8; i++) s += wred[i];
            sumsq[b * 384 + ch] = s;
        }
    }
}

// ---------------------------------------------------------------------------
// Raw S = q.k^T (24x24 per (b,head)), split-K over QKCH chunks.
// Compute loop unchanged (proven); staging now uint4 + half2->float2.
#define QKS 130
__global__ void qk_kernel(const __half* __restrict__ qkv, float* __restrict__ Spart)
{
    const int chunk = blockIdx.x;
    const int bh    = blockIdx.y;
    const int b = bh >> 3, h = bh & 7;
    const __half* qp = qkv + ((long)b * C3 + h * 24) * HW;
    const __half* kp = qkv + ((long)b * C3 + 192 + h * 24) * HW;
    __shared__ float qs[24 * QKS];
    __shared__ float ks[24 * QKS];
    const int t = threadIdx.x;
    unsigned long long a00 = 0ull, a01 = 0ull, a10 = 0ull, a11 = 0ull;
    const int cc = (t / 12) * 2;
    const int dd = (t % 12) * 2;
    int n0 = chunk * (HW / QKCH);
    const int iters = (HW / QKCH) / 128;
    for (int it = 0; it < iters; it++, n0 += 128) {
        // wide staging: 768 uint4 tasks (q: 0..383, k: 384..767)
#pragma unroll
        for (int j = 0; j < 3; j++) {
            int gi = j * 256 + t;
            int isk = gi >= 384;
            int li = isk ? gi - 384 : gi;
            int r = li >> 4, c16 = li & 15;
            const __half* src = (isk ? kp : qp) + (long)r * HW + n0 + c16 * 8;
            uint4 v = *(const uint4*)src;
            float* dst = (isk ? ks : qs) + r * QKS + c16 * 8;
            float2 f;
            f = __half22float2(*(__half2*)&v.x); *(float2*)&dst[0] = f;
            f = __half22float2(*(__half2*)&v.y); *(float2*)&dst[2] = f;
            f = __half22float2(*(__half2*)&v.z); *(float2*)&dst[4] = f;
            f = __half22float2(*(__half2*)&v.w); *(float2*)&dst[6] = f;
        }
        __syncthreads();
        if (t < 144) {
            const unsigned long long* q0p = (const unsigned long long*)&qs[cc * QKS];
            const unsigned long long* q1p = (const unsigned long long*)&qs[(cc + 1) * QKS];
            const unsigned long long* k0p = (const unsigned long long*)&ks[dd * QKS];
            const unsigned long long* k1p = (const unsigned long long*)&ks[(dd + 1) * QKS];
#pragma unroll 8
            for (int nn = 0; nn < 64; nn++) {
                unsigned long long q0 = q0p[nn];
                unsigned long long q1 = q1p[nn];
                unsigned long long k0 = k0p[nn];
                unsigned long long k1 = k1p[nn];
                fma2(a00, q0, k0); fma2(a01, q0, k1);
                fma2(a10, q1, k0); fma2(a11, q1, k1);
            }
        }
        __syncthreads();
    }
    if (t < 144) {
        float* sp = Spart + ((long)bh * QKCH + chunk) * 576;
        float2 v;
        v = unpack2(a00); sp[cc * 24 + dd]           = v.x + v.y;
        v = unpack2(a01); sp[cc * 24 + dd + 1]       = v.x + v.y;
        v = unpack2(a10); sp[(cc + 1) * 24 + dd]     = v.x + v.y;
        v = unpack2(a11); sp[(cc + 1) * 24 + dd + 1] = v.x + v.y;
    }
}

// ---------------------------------------------------------------------------
// Per batch: reduce split-K, normalize, softmax, fold w_proj -> packed fp16 W2.
__global__ void softmax_fold_kernel(const float* __restrict__ Spart,
                                    const float* __restrict__ sumsq,
                                    const float* __restrict__ temp,
                                    const float* __restrict__ wproj,
                                    unsigned* __restrict__ W2h)
{
    const int b = blockIdx.x;
    const int t = threadIdx.x;
    __shared__ float A[8 * 576];
    __shared__ float nq[192], nk[192];
    for (int i = t; i < 192; i += 256) {
        nq[i] = sqrtf(sumsq[b * 384 + i]) + 1e-6f;
        nk[i] = sqrtf(sumsq[b * 384 + 192 + i]) + 1e-6f;
    }
    __syncthreads();
    for (int idx = t; idx < 4608; idx += 256) {
        int h = idx / 576, r = idx % 576;
        int cidx = r / 24, d = r % 24;
        float s = 0.f;
#pragma unroll
        for (int ck = 0; ck < QKCH; ck++)
            s += Spart[(((long)b * 8 + h) * QKCH + ck) * 576 + r];
        A[idx] = s / (nq[h * 24 + cidx] * nk[h * 24 + d]) * temp[h];
    }
    __syncthreads();
    if (t < 192) {
        int h = t / 24, cidx = t % 24;
        float* row = &A[h * 576 + cidx * 24];
        float m = row[0];
        for (int d = 1; d < 24; d++) m = fmaxf(m, row[d]);
        float s = 0.f;
        for (int d = 0; d < 24; d++) { float e = expf(row[d] - m); row[d] = e; s += e; }
        float inv = 1.f / s;
        for (int d = 0; d < 24; d++) row[d] *= inv;
    }
    __syncthreads();
    for (int idx = t; idx < 192 * 96; idx += 256) {
        int o = idx / 96, j = idx % 96;
        int g0 = 2 * j;
        int h = g0 / 24, d0 = g0 % 24;
        float s0 = 0.f, s1 = 0.f;
#pragma unroll
        for (int cidx = 0; cidx < 24; cidx++) {
            float wv = wproj[o * CC + h * 24 + cidx];
            s0 += wv * A[h * 576 + cidx * 24 + d0];
            s1 += wv * A[h * 576 + cidx * 24 + d0 + 1];
        }
        W2h[((long)b * CC + o) * 96 + j] = pkh(s0, s1);
    }
}

// ---------------------------------------------------------------------------
extern "C" void kernel_launch(void* const* d_in, const int* in_sizes, int n_in,
                              void* d_out, int out_size)
{
    const float* x      = (const float*)d_in[0];
    const float* w_qkv  = (const float*)d_in[1];
    const float* w_dw   = (const float*)d_in[2];
    const float* w_proj = (const float*)d_in[3];
    const float* temp   = (const float*)d_in[4];
    float* out = (float*)d_out;

    __half *qkv_pre, *qkv_post;
    unsigned *wh, *W2h;
    float *sumsq, *Spart;
    cudaGetSymbolAddress((void**)&qkv_pre,  g_qkv_pre);
    cudaGetSymbolAddress((void**)&qkv_post, g_qkv_post);
    cudaGetSymbolAddress((void**)&wh,       g_wh);
    cudaGetSymbolAddress((void**)&W2h,      g_W2h);
    cudaGetSymbolAddress((void**)&sumsq,    g_sumsq);
    cudaGetSymbolAddress((void**)&Spart,    g_Spart);

    const int SMEM = (96 * BST + 64 * AST) * 4;  // 76288 B
    cudaFuncSetAttribute(gemm_nres,
                         cudaFuncAttributeMaxDynamicSharedMemorySize, SMEM);

    // pack w_qkv to fp16 k-pair layout (tiny)
    presplit_w<<<(576 * 96 + 255) / 256, 256>>>(w_qkv, wh);

    // K1: qkv = w_qkv @ x  -> fp16 (B resident, fp32 converted during staging)
    gemm_nres<<<dim3(HW / 128, NB), 256, SMEM>>>(
        wh, 0L, x, (long)CC * HW, qkv_pre, (long)C3 * HW, C3, HW, 2, 1);

    // K2: depthwise conv (plane-in-smem) + block-reduced sumsq
    dwconv_plane<<<dim3(C3, NB), 256>>>(qkv_pre, w_dw, qkv_post, sumsq);

    // K3: scalar f32x2 q.k^T (proven compute, wide staging)
    qk_kernel<<<dim3(QKCH, 64), 256>>>(qkv_post, Spart);

    // K4: normalize + softmax + fold -> packed fp16 W2
    softmax_fold_kernel<<<NB, 256>>>(Spart, sumsq, temp, w_proj, W2h);

    // K5: out = W2 @ v  (B = v resident fp16), fp32 out
    gemm_nres<<<dim3(HW / 128, NB), 256, SMEM>>>(
        W2h, (long)CC * 96, qkv_post + 384L * HW, (long)C3 * HW,
        out, (long)CC * HW, CC, HW, 1, 0);
}

// round 9
// speedup vs baseline: 4.7586x; 1.1731x over previous
#include <cuda_runtime.h>
#include <cuda_fp16.h>
#include <math.h>

// b=8, c=192, h=w=128, heads=8, ch=24, hw=16384, 3c=576
#define HW 16384
#define C3 576
#define CC 192
#define NB 8
#define QKCH 16

// Scratch (allocation-free rule: __device__ globals)
__device__ __half   g_qkv_pre[75497472];   // [8,576,16384] fp16
__device__ __half   g_qkv_post[75497472];  // [8,576,16384] fp16
__device__ unsigned g_wh[576 * 96];        // packed w_qkv
__device__ unsigned g_W2h[8 * 192 * 96];   // packed folded proj*attn
__device__ float    g_sumsq[8 * 384];
__device__ float    g_Spart[64 * QKCH * 576];

// ---------------------------------------------------------------------------
__device__ __forceinline__ unsigned pkh(float x, float y) {
    __half2 p = __floats2half2_rn(x, y);
    return *(unsigned*)&p;
}
__device__ __forceinline__ void fma2(unsigned long long& acc,
                                     unsigned long long a, unsigned long long b) {
    asm("fma.rn.f32x2 %0, %1, %2, %0;" : "+l"(acc) : "l"(a), "l"(b));
}
__device__ __forceinline__ float2 unpack2(unsigned long long p) {
    unsigned lo, hi;
    asm("mov.b64 {%0, %1}, %2;" : "=r"(lo), "=r"(hi) : "l"(p));
    return make_float2(__uint_as_float(lo), __uint_as_float(hi));
}
__device__ __forceinline__ void mma_f16(float* c, const unsigned* a,
                                        unsigned b0, unsigned b1) {
    asm("mma.sync.aligned.m16n8k16.row.col.f32.f16.f16.f32 "
        "{%0,%1,%2,%3}, {%4,%5,%6,%7}, {%8,%9}, {%0,%1,%2,%3};"
        : "+f"(c[0]), "+f"(c[1]), "+f"(c[2]), "+f"(c[3])
        : "r"(a[0]), "r"(a[1]), "r"(a[2]), "r"(a[3]), "r"(b0), "r"(b1));
}

// ---------------------------------------------------------------------------
// w_qkv fp32 [576][192] -> packed u32 [576][96]
__global__ void presplit_w(const float* __restrict__ w, unsigned* __restrict__ wh)
{
    int i = blockIdx.x * 256 + threadIdx.x;
    if (i >= 576 * 96) return;
    int o = i / 96, j = i % 96;
    float2 v = *(const float2*)&w[o * CC + 2 * j];
    wh[i] = pkh(v.x, v.y);
}

// ---------------------------------------------------------------------------
// B-resident fp16 tensor-core GEMM. K fixed = 192. (proven, unchanged)
#define BST 132   // Bs row stride (u32)
#define AST 100   // As row stride (u32)
__global__ __launch_bounds__(256)
void gemm_nres(const unsigned* __restrict__ Apk, long aBS,
               const void* __restrict__ Bv, long bBS,
               void* __restrict__ Ov, long oBS,
               int M, int N, int BMODE, int HALF_OUT)
{
    extern __shared__ unsigned sh[];
    unsigned* Bs = sh;                 // [96][BST]
    unsigned* As = sh + 96 * BST;      // [64][AST]

    const int b = blockIdx.y;
    const int n0 = blockIdx.x * 128;
    const unsigned* Ab = Apk + aBS * b;
    const int t = threadIdx.x;
    const int wid = t >> 5, lane = t & 31;
    const int g = lane >> 2, tig = lane & 3;
    const int warp_m = wid >> 2, warp_n = wid & 3;

    if (BMODE == 2) {
        const float* Bf = (const float*)Bv + bBS * b;
#pragma unroll
        for (int j = 0; j < 12; j++) {
            int gi = j * 256 + t;
            int pr = gi >> 5;
            int nc = (gi & 31) * 4;
            const float* base = Bf + (long)(2 * pr) * N + n0 + nc;
            float4 u = *(const float4*)base;
            float4 v = *(const float4*)(base + N);
            Bs[pr * BST + nc + 0] = pkh(u.x, v.x);
            Bs[pr * BST + nc + 1] = pkh(u.y, v.y);
            Bs[pr * BST + nc + 2] = pkh(u.z, v.z);
            Bs[pr * BST + nc + 3] = pkh(u.w, v.w);
        }
    } else {
        const __half* Bh = (const __half*)Bv + bBS * b;
#pragma unroll
        for (int j = 0; j < 12; j++) {
            int gi = j * 256 + t;
            int pr = gi >> 5;
            int nc = (gi & 31) * 4;
            const __half* base = Bh + (long)(2 * pr) * N + n0 + nc;
            uint2 a = *(const uint2*)base;
            uint2 bb = *(const uint2*)(base + N);
            Bs[pr * BST + nc + 0] = __byte_perm(a.x, bb.x, 0x5410);
            Bs[pr * BST + nc + 1] = __byte_perm(a.x, bb.x, 0x7632);
            Bs[pr * BST + nc + 2] = __byte_perm(a.y, bb.y, 0x5410);
            Bs[pr * BST + nc + 3] = __byte_perm(a.y, bb.y, 0x7632);
        }
    }
    __syncthreads();

    const int mtiles = M / 64;
    for (int mt = 0; mt < mtiles; mt++) {
        const int m0 = mt * 64;
#pragma unroll
        for (int j = 0; j < 6; j++) {
            int gi = j * 256 + t;
            int row = gi / 24;
            int kq = (gi % 24) * 4;
            uint4 v = *(const uint4*)&Ab[(long)(m0 + row) * 96 + kq];
            *(uint4*)&As[row * AST + kq] = v;
        }
        __syncthreads();

        float c[2][4][4];
#pragma unroll
        for (int i = 0; i < 2; i++)
#pragma unroll
            for (int j = 0; j < 4; j++)
#pragma unroll
                for (int q = 0; q < 4; q++) c[i][j][q] = 0.f;

#pragma unroll
        for (int kp0 = 0; kp0 < 96; kp0 += 8) {
            unsigned a[2][4];
#pragma unroll
            for (int m2 = 0; m2 < 2; m2++) {
                int rb = warp_m * 32 + m2 * 16;
                a[m2][0] = As[(rb + g) * AST + kp0 + tig];
                a[m2][1] = As[(rb + g + 8) * AST + kp0 + tig];
                a[m2][2] = As[(rb + g) * AST + kp0 + tig + 4];
                a[m2][3] = As[(rb + g + 8) * AST + kp0 + tig + 4];
            }
#pragma unroll
            for (int nt = 0; nt < 4; nt++) {
                int gc = warp_n * 32 + nt * 8 + g;
                unsigned b0 = Bs[(kp0 + tig) * BST + gc];
                unsigned b1 = Bs[(kp0 + tig + 4) * BST + gc];
#pragma unroll
                for (int m2 = 0; m2 < 2; m2++)
                    mma_f16(c[m2][nt], a[m2], b0, b1);
            }
        }

#pragma unroll
        for (int m2 = 0; m2 < 2; m2++) {
            int row = m0 + warp_m * 32 + m2 * 16 + g;
#pragma unroll
            for (int nt = 0; nt < 4; nt++) {
                int col = n0 + warp_n * 32 + nt * 8 + 2 * tig;
                if (HALF_OUT) {
                    __half* Oh = (__half*)Ov + oBS * b;
                    *(unsigned*)&Oh[(long)row * N + col] =
                        pkh(c[m2][nt][0], c[m2][nt][1]);
                    *(unsigned*)&Oh[(long)(row + 8) * N + col] =
                        pkh(c[m2][nt][2], c[m2][nt][3]);
                } else {
                    float* Of = (float*)Ov + oBS * b;
                    *(float2*)&Of[(long)row * N + col] =
                        make_float2(c[m2][nt][0], c[m2][nt][1]);
                    *(float2*)&Of[(long)(row + 8) * N + col] =
                        make_float2(c[m2][nt][2], c[m2][nt][3]);
                }
            }
        }
        __syncthreads();
    }
}

// ---------------------------------------------------------------------------
// Depthwise 3x3 conv (dilation 2, pad 2): one block per (ch, b) plane. (proven)
__global__ __launch_bounds__(256)
void dwconv_plane(const __half* __restrict__ in,
                  const float* __restrict__ wdw,
                  __half* __restrict__ out,
                  float* __restrict__ sumsq)
{
    __shared__ __half sp[16384];
    __shared__ float wred[8];
    const int ch = blockIdx.x;
    const int b  = blockIdx.y;
    const int t  = threadIdx.x;
    const __half* ip = in + ((long)b * C3 + ch) * HW;

#pragma unroll
    for (int i = 0; i < 8; i++) {
        int off = (i * 256 + t) * 8;
        *(uint4*)&sp[off] = *(const uint4*)&ip[off];
    }
    float w[9];
#pragma unroll
    for (int i = 0; i < 9; i++) w[i] = __ldg(&wdw[ch * 9 + i]);
    __syncthreads();

    const __half2* sp2 = (const __half2*)sp;
    unsigned* op = (unsigned*)(out + ((long)b * C3 + ch) * HW);
    float ss = 0.f;

#pragma unroll 4
    for (int i = 0; i < 32; i++) {
        int p = i * 512 + t * 2;
        int y = p >> 7, x = p & 127;
        float a0 = 0.f, a1 = 0.f;
#pragma unroll
        for (int r = 0; r < 3; r++) {
            int yy = y + 2 * (r - 1);
            if (yy < 0 || yy >= 128) continue;
            int ro = yy * 64;
            float2 p0 = (x >= 2)
                ? __half22float2(sp2[ro + ((x - 2) >> 1)]) : make_float2(0.f, 0.f);
            float2 p1 = __half22float2(sp2[ro + (x >> 1)]);
            float2 p2 = (x <= 124)
                ? __half22float2(sp2[ro + ((x + 2) >> 1)]) : make_float2(0.f, 0.f);
            float w0 = w[r * 3 + 0], w1 = w[r * 3 + 1], w2 = w[r * 3 + 2];
            a0 += w0 * p0.x + w1 * p1.x + w2 * p2.x;
            a1 += w0 * p0.y + w1 * p1.y + w2 * p2.y;
        }
        op[p >> 1] = pkh(a0, a1);
        ss += a0 * a0 + a1 * a1;
    }

    if (ch < 384) {
#pragma unroll
        for (int off = 16; off; off >>= 1)
            ss += __shfl_down_sync(0xffffffffu, ss, off);
        if ((t & 31) == 0) wred[t >> 5] = ss;
        __syncthreads();
        if (t == 0) {
            float s = 0.f;
#pragma unroll
            for (int i = 0; i < 8; i++) s += wred[i];
            sumsq[b * 384 + ch] = s;
        }
    }
}

// ---------------------------------------------------------------------------
// Raw S = q.k^T (24x24 per (b,head)), split-K over QKCH chunks.
// 3x3 register tile over 64-thread groups; 4 groups per block, each owning a
// 32-wide spatial slice of the staged 128-chunk. LDS.128 loads, no atomics.
#define QKS 132
__global__ __launch_bounds__(256)
void qk_kernel(const __half* __restrict__ qkv, float* __restrict__ Spart)
{
    __shared__ float qs[24 * QKS];
    __shared__ float ks[24 * QKS];
    __shared__ float Sred[4][576];

    const int chunk = blockIdx.x;
    const int bh    = blockIdx.y;
    const int b = bh >> 3, h = bh & 7;
    const __half* qp = qkv + ((long)b * C3 + h * 24) * HW;
    const __half* kp = qkv + ((long)b * C3 + 192 + h * 24) * HW;
    const int t = threadIdx.x;
    const int wp = t >> 6;            // spatial slice group 0..3
    const int t64 = t & 63;
    const int cc = (t64 >> 3) * 3;    // 0,3,...,21
    const int dd = (t64 & 7) * 3;     // 0,3,...,21

    unsigned long long a[3][3];
#pragma unroll
    for (int i = 0; i < 3; i++)
#pragma unroll
        for (int j = 0; j < 3; j++) a[i][j] = 0ull;

    int n0 = chunk * (HW / QKCH);
    const int iters = (HW / QKCH) / 128;
    for (int it = 0; it < iters; it++, n0 += 128) {
        // stage: 768 uint4 tasks (q: 0..383, k: 384..767), fp16 -> fp32
#pragma unroll
        for (int j = 0; j < 3; j++) {
            int gi = j * 256 + t;
            int isk = gi >= 384;
            int li = isk ? gi - 384 : gi;
            int r = li >> 4, c16 = li & 15;
            const __half* src = (isk ? kp : qp) + (long)r * HW + n0 + c16 * 8;
            uint4 v = *(const uint4*)src;
            float* dst = (isk ? ks : qs) + r * QKS + c16 * 8;
            float2 f;
            f = __half22float2(*(__half2*)&v.x); *(float2*)&dst[0] = f;
            f = __half22float2(*(__half2*)&v.y); *(float2*)&dst[2] = f;
            f = __half22float2(*(__half2*)&v.z); *(float2*)&dst[4] = f;
            f = __half22float2(*(__half2*)&v.w); *(float2*)&dst[6] = f;
        }
        __syncthreads();

        // group wp handles spatial [wp*32, wp*32+32): 8 steps of 4 floats
#pragma unroll
        for (int s = 0; s < 8; s++) {
            int nb = wp * 32 + s * 4;
            ulonglong2 q0 = *(const ulonglong2*)&qs[cc * QKS + nb];
            ulonglong2 q1 = *(const ulonglong2*)&qs[(cc + 1) * QKS + nb];
            ulonglong2 q2 = *(const ulonglong2*)&qs[(cc + 2) * QKS + nb];
            ulonglong2 k0 = *(const ulonglong2*)&ks[dd * QKS + nb];
            ulonglong2 k1 = *(const ulonglong2*)&ks[(dd + 1) * QKS + nb];
            ulonglong2 k2 = *(const ulonglong2*)&ks[(dd + 2) * QKS + nb];
            fma2(a[0][0], q0.x, k0.x); fma2(a[0][0], q0.y, k0.y);
            fma2(a[0][1], q0.x, k1.x); fma2(a[0][1], q0.y, k1.y);
            fma2(a[0][2], q0.x, k2.x); fma2(a[0][2], q0.y, k2.y);
            fma2(a[1][0], q1.x, k0.x); fma2(a[1][0], q1.y, k0.y);
            fma2(a[1][1], q1.x, k1.x); fma2(a[1][1], q1.y, k1.y);
            fma2(a[1][2], q1.x, k2.x); fma2(a[1][2], q1.y, k2.y);
            fma2(a[2][0], q2.x, k0.x); fma2(a[2][0], q2.y, k0.y);
            fma2(a[2][1], q2.x, k1.x); fma2(a[2][1], q2.y, k1.y);
            fma2(a[2][2], q2.x, k2.x); fma2(a[2][2], q2.y, k2.y);
        }
        __syncthreads();
    }

    // per-group private slabs (each (c,d) touched by exactly one thread/group)
#pragma unroll
    for (int i = 0; i < 3; i++)
#pragma unroll
        for (int j = 0; j < 3; j++) {
            float2 v = unpack2(a[i][j]);
            Sred[wp][(cc + i) * 24 + dd + j] = v.x + v.y;
        }
    __syncthreads();

    float* sp = Spart + ((long)bh * QKCH + chunk) * 576;
    for (int i = t; i < 576; i += 256)
        sp[i] = (Sred[0][i] + Sred[1][i]) + (Sred[2][i] + Sred[3][i]);
}

// ---------------------------------------------------------------------------
// Per batch: reduce split-K, normalize, softmax, fold w_proj -> packed fp16 W2.
__global__ void softmax_fold_kernel(const float* __restrict__ Spart,
                                    const float* __restrict__ sumsq,
                                    const float* __restrict__ temp,
                                    const float* __restrict__ wproj,
                                    unsigned* __restrict__ W2h)
{
    const int b = blockIdx.x;
    const int t = threadIdx.x;
    __shared__ float A[8 * 576];
    __shared__ float nq[192], nk[192];
    for (int i = t; i < 192; i += 256) {
        nq[i] = sqrtf(sumsq[b * 384 + i]) + 1e-6f;
        nk[i] = sqrtf(sumsq[b * 384 + 192 + i]) + 1e-6f;
    }
    __syncthreads();
    for (int idx = t; idx < 4608; idx += 256) {
        int h = idx / 576, r = idx % 576;
        int cidx = r / 24, d = r % 24;
        float s = 0.f;
#pragma unroll
        for (int ck = 0; ck < QKCH; ck++)
            s += Spart[(((long)b * 8 + h) * QKCH + ck) * 576 + r];
        A[idx] = s / (nq[h * 24 + cidx] * nk[h * 24 + d]) * temp[h];
    }
    __syncthreads();
    if (t < 192) {
        int h = t / 24, cidx = t % 24;
        float* row = &A[h * 576 + cidx * 24];
        float m = row[0];
        for (int d = 1; d < 24; d++) m = fmaxf(m, row[d]);
        float s = 0.f;
        for (int d = 0; d < 24; d++) { float e = expf(row[d] - m); row[d] = e; s += e; }
        float inv = 1.f / s;
        for (int d = 0; d < 24; d++) row[d] *= inv;
    }
    __syncthreads();
    for (int idx = t; idx < 192 * 96; idx += 256) {
        int o = idx / 96, j = idx % 96;
        int g0 = 2 * j;
        int h = g0 / 24, d0 = g0 % 24;
        float s0 = 0.f, s1 = 0.f;
#pragma unroll
        for (int cidx = 0; cidx < 24; cidx++) {
            float wv = wproj[o * CC + h * 24 + cidx];
            s0 += wv * A[h * 576 + cidx * 24 + d0];
            s1 += wv * A[h * 576 + cidx * 24 + d0 + 1];
        }
        W2h[((long)b * CC + o) * 96 + j] = pkh(s0, s1);
    }
}

// ---------------------------------------------------------------------------
extern "C" void kernel_launch(void* const* d_in, const int* in_sizes, int n_in,
                              void* d_out, int out_size)
{
    const float* x      = (const float*)d_in[0];
    const float* w_qkv  = (const float*)d_in[1];
    const float* w_dw   = (const float*)d_in[2];
    const float* w_proj = (const float*)d_in[3];
    const float* temp   = (const float*)d_in[4];
    float* out = (float*)d_out;

    __half *qkv_pre, *qkv_post;
    unsigned *wh, *W2h;
    float *sumsq, *Spart;
    cudaGetSymbolAddress((void**)&qkv_pre,  g_qkv_pre);
    cudaGetSymbolAddress((void**)&qkv_post, g_qkv_post);
    cudaGetSymbolAddress((void**)&wh,       g_wh);
    cudaGetSymbolAddress((void**)&W2h,      g_W2h);
    cudaGetSymbolAddress((void**)&sumsq,    g_sumsq);
    cudaGetSymbolAddress((void**)&Spart,    g_Spart);

    const int SMEM = (96 * BST + 64 * AST) * 4;  // 76288 B
    cudaFuncSetAttribute(gemm_nres,
                         cudaFuncAttributeMaxDynamicSharedMemorySize, SMEM);

    presplit_w<<<(576 * 96 + 255) / 256, 256>>>(w_qkv, wh);

    // K1: qkv = w_qkv @ x  -> fp16 (B resident, fp32 converted during staging)
    gemm_nres<<<dim3(HW / 128, NB), 256, SMEM>>>(
        wh, 0L, x, (long)CC * HW, qkv_pre, (long)C3 * HW, C3, HW, 2, 1);

    // K2: depthwise conv (plane-in-smem) + block-reduced sumsq
    dwconv_plane<<<dim3(C3, NB), 256>>>(qkv_pre, w_dw, qkv_post, sumsq);

    // K3: q.k^T, 3x3 tile, all-thread
    qk_kernel<<<dim3(QKCH, 64), 256>>>(qkv_post, Spart);

    // K4: normalize + softmax + fold -> packed fp16 W2
    softmax_fold_kernel<<<NB, 256>>>(Spart, sumsq, temp, w_proj, W2h);

    // K5: out = W2 @ v  (B = v resident fp16), fp32 out
    gemm_nres<<<dim3(HW / 128, NB), 256, SMEM>>>(
        W2h, (long)CC * 96, qkv_post + 384L * HW, (long)C3 * HW,
        out, (long)CC * HW, CC, HW, 1, 0);
}

// round 10
// speedup vs baseline: 5.6493x; 1.1872x over previous
#include <cuda_runtime.h>
#include <cuda_fp16.h>
#include <math.h>

// b=8, c=192, h=w=128, heads=8, ch=24, hw=16384, 3c=576
#define HW 16384
#define C3 576
#define CC 192
#define NB 8
#define QKCH 16

// Scratch (allocation-free rule: __device__ globals)
__device__ __half   g_qkv_pre[75497472];   // [8,576,16384] fp16
__device__ __half   g_qkv_post[75497472];  // [8,576,16384] fp16
__device__ unsigned g_wh[576 * 96];        // packed w_qkv
__device__ unsigned g_W2h[8 * 192 * 96];   // packed folded proj*attn
__device__ float    g_sumsq[8 * 384];
__device__ float    g_Spart[64 * QKCH * 576];

// ---------------------------------------------------------------------------
__device__ __forceinline__ unsigned pkh(float x, float y) {
    __half2 p = __floats2half2_rn(x, y);
    return *(unsigned*)&p;
}
__device__ __forceinline__ void fma2(unsigned long long& acc,
                                     unsigned long long a, unsigned long long b) {
    asm("fma.rn.f32x2 %0, %1, %2, %0;" : "+l"(acc) : "l"(a), "l"(b));
}
__device__ __forceinline__ float2 unpack2(unsigned long long p) {
    unsigned lo, hi;
    asm("mov.b64 {%0, %1}, %2;" : "=r"(lo), "=r"(hi) : "l"(p));
    return make_float2(__uint_as_float(lo), __uint_as_float(hi));
}
__device__ __forceinline__ void mma_f16(float* c, const unsigned* a,
                                        unsigned b0, unsigned b1) {
    asm("mma.sync.aligned.m16n8k16.row.col.f32.f16.f16.f32 "
        "{%0,%1,%2,%3}, {%4,%5,%6,%7}, {%8,%9}, {%0,%1,%2,%3};"
        : "+f"(c[0]), "+f"(c[1]), "+f"(c[2]), "+f"(c[3])
        : "r"(a[0]), "r"(a[1]), "r"(a[2]), "r"(a[3]), "r"(b0), "r"(b1));
}

// ---------------------------------------------------------------------------
// w_qkv fp32 [576][192] -> packed u32 [576][96]
__global__ void presplit_w(const float* __restrict__ w, unsigned* __restrict__ wh)
{
    int i = blockIdx.x * 256 + threadIdx.x;
    if (i >= 576 * 96) return;
    int o = i / 96, j = i % 96;
    float2 v = *(const float2*)&w[o * CC + 2 * j];
    wh[i] = pkh(v.x, v.y);
}

// ---------------------------------------------------------------------------
// B-resident fp16 tensor-core GEMM. K fixed = 192.
// BST=136 (==8 mod 32): conflict-free B fragment loads.
// As double-buffered: next m-tile's A prefetched during mainloop.
#define BST 136   // Bs row stride (u32)
#define AST 100   // As row stride (u32)
#define ABUF (64 * AST)
__global__ __launch_bounds__(256)
void gemm_nres(const unsigned* __restrict__ Apk, long aBS,
               const void* __restrict__ Bv, long bBS,
               void* __restrict__ Ov, long oBS,
               int M, int N, int BMODE, int HALF_OUT)
{
    extern __shared__ unsigned sh[];
    unsigned* Bs = sh;                 // [96][BST]
    unsigned* As = sh + 96 * BST;      // 2 x [64][AST]

    const int b = blockIdx.y;
    const int n0 = blockIdx.x * 128;
    const unsigned* Ab = Apk + aBS * b;
    const int t = threadIdx.x;
    const int wid = t >> 5, lane = t & 31;
    const int g = lane >> 2, tig = lane & 3;
    const int warp_m = wid >> 2, warp_n = wid & 3;

    // ---- stage full B tile (192 k x 128 n) as packed u32 k-pairs ----
    if (BMODE == 2) {
        const float* Bf = (const float*)Bv + bBS * b;
#pragma unroll
        for (int j = 0; j < 12; j++) {
            int gi = j * 256 + t;
            int pr = gi >> 5;
            int nc = (gi & 31) * 4;
            const float* base = Bf + (long)(2 * pr) * N + n0 + nc;
            float4 u = *(const float4*)base;
            float4 v = *(const float4*)(base + N);
            *(uint4*)&Bs[pr * BST + nc] =
                make_uint4(pkh(u.x, v.x), pkh(u.y, v.y), pkh(u.z, v.z), pkh(u.w, v.w));
        }
    } else {
        const __half* Bh = (const __half*)Bv + bBS * b;
#pragma unroll
        for (int j = 0; j < 12; j++) {
            int gi = j * 256 + t;
            int pr = gi >> 5;
            int nc = (gi & 31) * 4;
            const __half* base = Bh + (long)(2 * pr) * N + n0 + nc;
            uint2 a = *(const uint2*)base;
            uint2 bb = *(const uint2*)(base + N);
            *(uint4*)&Bs[pr * BST + nc] =
                make_uint4(__byte_perm(a.x, bb.x, 0x5410), __byte_perm(a.x, bb.x, 0x7632),
                           __byte_perm(a.y, bb.y, 0x5410), __byte_perm(a.y, bb.y, 0x7632));
        }
    }
    // ---- stage A tile 0 ----
    {
        int row = (t * 6) / 1536 * 0; // (dummy to keep layout simple below)
    }
#pragma unroll
    for (int j = 0; j < 6; j++) {
        int gi = j * 256 + t;
        int row = gi / 24;
        int kq = (gi % 24) * 4;
        uint4 v = *(const uint4*)&Ab[(long)row * 96 + kq];
        *(uint4*)&As[row * AST + kq] = v;
    }
    __syncthreads();

    const int mtiles = M / 64;
    int buf = 0;
    for (int mt = 0; mt < mtiles; mt++) {
        const int m0 = mt * 64;
        const bool hasNext = (mt + 1 < mtiles);
        // prefetch next A tile into regs
        uint4 pf[6];
        if (hasNext) {
#pragma unroll
            for (int j = 0; j < 6; j++) {
                int gi = j * 256 + t;
                int row = gi / 24;
                int kq = (gi % 24) * 4;
                pf[j] = *(const uint4*)&Ab[(long)(m0 + 64 + row) * 96 + kq];
            }
        }

        float c[2][4][4];
#pragma unroll
        for (int i = 0; i < 2; i++)
#pragma unroll
            for (int j = 0; j < 4; j++)
#pragma unroll
                for (int q = 0; q < 4; q++) c[i][j][q] = 0.f;

        const unsigned* Ax = As + buf * ABUF;
#pragma unroll
        for (int kp0 = 0; kp0 < 96; kp0 += 8) {
            unsigned a[2][4];
#pragma unroll
            for (int m2 = 0; m2 < 2; m2++) {
                int rb = warp_m * 32 + m2 * 16;
                a[m2][0] = Ax[(rb + g) * AST + kp0 + tig];
                a[m2][1] = Ax[(rb + g + 8) * AST + kp0 + tig];
                a[m2][2] = Ax[(rb + g) * AST + kp0 + tig + 4];
                a[m2][3] = Ax[(rb + g + 8) * AST + kp0 + tig + 4];
            }
#pragma unroll
            for (int nt = 0; nt < 4; nt++) {
                int gc = warp_n * 32 + nt * 8 + g;
                unsigned b0 = Bs[(kp0 + tig) * BST + gc];
                unsigned b1 = Bs[(kp0 + tig + 4) * BST + gc];
#pragma unroll
                for (int m2 = 0; m2 < 2; m2++)
                    mma_f16(c[m2][nt], a[m2], b0, b1);
            }
        }

        // store prefetched A into alternate buffer (nobody reads it yet)
        if (hasNext) {
#pragma unroll
            for (int j = 0; j < 6; j++) {
                int gi = j * 256 + t;
                int row = gi / 24;
                int kq = (gi % 24) * 4;
                *(uint4*)&As[(buf ^ 1) * ABUF + row * AST + kq] = pf[j];
            }
        }

        // epilogue
#pragma unroll
        for (int m2 = 0; m2 < 2; m2++) {
            int row = m0 + warp_m * 32 + m2 * 16 + g;
#pragma unroll
            for (int nt = 0; nt < 4; nt++) {
                int col = n0 + warp_n * 32 + nt * 8 + 2 * tig;
                if (HALF_OUT) {
                    __half* Oh = (__half*)Ov + oBS * b;
                    *(unsigned*)&Oh[(long)row * N + col] =
                        pkh(c[m2][nt][0], c[m2][nt][1]);
                    *(unsigned*)&Oh[(long)(row + 8) * N + col] =
                        pkh(c[m2][nt][2], c[m2][nt][3]);
                } else {
                    float* Of = (float*)Ov + oBS * b;
                    *(float2*)&Of[(long)row * N + col] =
                        make_float2(c[m2][nt][0], c[m2][nt][1]);
                    *(float2*)&Of[(long)(row + 8) * N + col] =
                        make_float2(c[m2][nt][2], c[m2][nt][3]);
                }
            }
        }
        __syncthreads();
        buf ^= 1;
    }
}

// ---------------------------------------------------------------------------
// Depthwise 3x3 conv (dilation 2, pad 2): one block per (ch, b) plane. (proven)
__global__ __launch_bounds__(256)
void dwconv_plane(const __half* __restrict__ in,
                  const float* __restrict__ wdw,
                  __half* __restrict__ out,
                  float* __restrict__ sumsq)
{
    __shared__ __half sp[16384];
    __shared__ float wred[8];
    const int ch = blockIdx.x;
    const int b  = blockIdx.y;
    const int t  = threadIdx.x;
    const __half* ip = in + ((long)b * C3 + ch) * HW;

#pragma unroll
    for (int i = 0; i < 8; i++) {
        int off = (i * 256 + t) * 8;
        *(uint4*)&sp[off] = *(const uint4*)&ip[off];
    }
    float w[9];
#pragma unroll
    for (int i = 0; i < 9; i++) w[i] = __ldg(&wdw[ch * 9 + i]);
    __syncthreads();

    const __half2* sp2 = (const __half2*)sp;
    unsigned* op = (unsigned*)(out + ((long)b * C3 + ch) * HW);
    float ss = 0.f;

#pragma unroll 4
    for (int i = 0; i < 32; i++) {
        int p = i * 512 + t * 2;
        int y = p >> 7, x = p & 127;
        float a0 = 0.f, a1 = 0.f;
#pragma unroll
        for (int r = 0; r < 3; r++) {
            int yy = y + 2 * (r - 1);
            if (yy < 0 || yy >= 128) continue;
            int ro = yy * 64;
            float2 p0 = (x >= 2)
                ? __half22float2(sp2[ro + ((x - 2) >> 1)]) : make_float2(0.f, 0.f);
            float2 p1 = __half22float2(sp2[ro + (x >> 1)]);
            float2 p2 = (x <= 124)
                ? __half22float2(sp2[ro + ((x + 2) >> 1)]) : make_float2(0.f, 0.f);
            float w0 = w[r * 3 + 0], w1 = w[r * 3 + 1], w2 = w[r * 3 + 2];
            a0 += w0 * p0.x + w1 * p1.x + w2 * p2.x;
            a1 += w0 * p0.y + w1 * p1.y + w2 * p2.y;
        }
        op[p >> 1] = pkh(a0, a1);
        ss += a0 * a0 + a1 * a1;
    }

    if (ch < 384) {
#pragma unroll
        for (int off = 16; off; off >>= 1)
            ss += __shfl_down_sync(0xffffffffu, ss, off);
        if ((t & 31) == 0) wred[t >> 5] = ss;
        __syncthreads();
        if (t == 0) {
            float s = 0.f;
#pragma unroll
            for (int i = 0; i < 8; i++) s += wred[i];
            sumsq[b * 384 + ch] = s;
        }
    }
}

// ---------------------------------------------------------------------------
// Raw S = q.k^T: 3x3 tile over 64-thread groups. (proven, unchanged)
#define QKS 132
__global__ __launch_bounds__(256)
void qk_kernel(const __half* __restrict__ qkv, float* __restrict__ Spart)
{
    __shared__ float qs[24 * QKS];
    __shared__ float ks[24 * QKS];
    __shared__ float Sred[4][576];

    const int chunk = blockIdx.x;
    const int bh    = blockIdx.y;
    const int b = bh >> 3, h = bh & 7;
    const __half* qp = qkv + ((long)b * C3 + h * 24) * HW;
    const __half* kp = qkv + ((long)b * C3 + 192 + h * 24) * HW;
    const int t = threadIdx.x;
    const int wp = t >> 6;
    const int t64 = t & 63;
    const int cc = (t64 >> 3) * 3;
    const int dd = (t64 & 7) * 3;

    unsigned long long a[3][3];
#pragma unroll
    for (int i = 0; i < 3; i++)
#pragma unroll
        for (int j = 0; j < 3; j++) a[i][j] = 0ull;

    int n0 = chunk * (HW / QKCH);
    const int iters = (HW / QKCH) / 128;
    for (int it = 0; it < iters; it++, n0 += 128) {
#pragma unroll
        for (int j = 0; j < 3; j++) {
            int gi = j * 256 + t;
            int isk = gi >= 384;
            int li = isk ? gi - 384 : gi;
            int r = li >> 4, c16 = li & 15;
            const __half* src = (isk ? kp : qp) + (long)r * HW + n0 + c16 * 8;
            uint4 v = *(const uint4*)src;
            float* dst = (isk ? ks : qs) + r * QKS + c16 * 8;
            float2 f;
            f = __half22float2(*(__half2*)&v.x); *(float2*)&dst[0] = f;
            f = __half22float2(*(__half2*)&v.y); *(float2*)&dst[2] = f;
            f = __half22float2(*(__half2*)&v.z); *(float2*)&dst[4] = f;
            f = __half22float2(*(__half2*)&v.w); *(float2*)&dst[6] = f;
        }
        __syncthreads();

#pragma unroll
        for (int s = 0; s < 8; s++) {
            int nb = wp * 32 + s * 4;
            ulonglong2 q0 = *(const ulonglong2*)&qs[cc * QKS + nb];
            ulonglong2 q1 = *(const ulonglong2*)&qs[(cc + 1) * QKS + nb];
            ulonglong2 q2 = *(const ulonglong2*)&qs[(cc + 2) * QKS + nb];
            ulonglong2 k0 = *(const ulonglong2*)&ks[dd * QKS + nb];
            ulonglong2 k1 = *(const ulonglong2*)&ks[(dd + 1) * QKS + nb];
            ulonglong2 k2 = *(const ulonglong2*)&ks[(dd + 2) * QKS + nb];
            fma2(a[0][0], q0.x, k0.x); fma2(a[0][0], q0.y, k0.y);
            fma2(a[0][1], q0.x, k1.x); fma2(a[0][1], q0.y, k1.y);
            fma2(a[0][2], q0.x, k2.x); fma2(a[0][2], q0.y, k2.y);
            fma2(a[1][0], q1.x, k0.x); fma2(a[1][0], q1.y, k0.y);
            fma2(a[1][1], q1.x, k1.x); fma2(a[1][1], q1.y, k1.y);
            fma2(a[1][2], q1.x, k2.x); fma2(a[1][2], q1.y, k2.y);
            fma2(a[2][0], q2.x, k0.x); fma2(a[2][0], q2.y, k0.y);
            fma2(a[2][1], q2.x, k1.x); fma2(a[2][1], q2.y, k1.y);
            fma2(a[2][2], q2.x, k2.x); fma2(a[2][2], q2.y, k2.y);
        }
        __syncthreads();
    }

#pragma unroll
    for (int i = 0; i < 3; i++)
#pragma unroll
        for (int j = 0; j < 3; j++) {
            float2 v = unpack2(a[i][j]);
            Sred[wp][(cc + i) * 24 + dd + j] = v.x + v.y;
        }
    __syncthreads();

    float* sp = Spart + ((long)bh * QKCH + chunk) * 576;
    for (int i = t; i < 576; i += 256)
        sp[i] = (Sred[0][i] + Sred[1][i]) + (Sred[2][i] + Sred[3][i]);
}

// ---------------------------------------------------------------------------
// Per (b,head): reduce split-K, normalize, softmax, fold w_proj -> fp16 W2.
// 64 blocks (8x parallelism vs per-batch); identical arithmetic per output.
__global__ void softmax_fold_kernel(const float* __restrict__ Spart,
                                    const float* __restrict__ sumsq,
                                    const float* __restrict__ temp,
                                    const float* __restrict__ wproj,
                                    unsigned* __restrict__ W2h)
{
    const int bh = blockIdx.x;          // 0..63
    const int b = bh >> 3, h = bh & 7;
    const int t = threadIdx.x;          // 256
    __shared__ float A[576];
    __shared__ float nq[24], nk[24];
    if (t < 24)
        nq[t] = sqrtf(sumsq[b * 384 + h * 24 + t]) + 1e-6f;
    else if (t < 48)
        nk[t - 24] = sqrtf(sumsq[b * 384 + 192 + h * 24 + (t - 24)]) + 1e-6f;
    __syncthreads();
    const float tmp = temp[h];
    for (int r = t; r < 576; r += 256) {
        int cidx = r / 24, d = r % 24;
        float s = 0.f;
#pragma unroll
        for (int ck = 0; ck < QKCH; ck++)
            s += Spart[((long)bh * QKCH + ck) * 576 + r];
        A[r] = s / (nq[cidx] * nk[d]) * tmp;
    }
    __syncthreads();
    if (t < 24) {
        float* row = &A[t * 24];
        float m = row[0];
        for (int d = 1; d < 24; d++) m = fmaxf(m, row[d]);
        float s = 0.f;
        for (int d = 0; d < 24; d++) { float e = expf(row[d] - m); row[d] = e; s += e; }
        float inv = 1.f / s;
        for (int d = 0; d < 24; d++) row[d] *= inv;
    }
    __syncthreads();
    // this head's W2 columns: j in [h*12, h*12+12), d0 = 2*(j - h*12)
    for (int idx = t; idx < 192 * 12; idx += 256) {
        int o = idx / 12, jj = idx % 12;
        int d0 = 2 * jj;
        float s0 = 0.f, s1 = 0.f;
#pragma unroll
        for (int cidx = 0; cidx < 24; cidx++) {
            float wv = wproj[o * CC + h * 24 + cidx];
            s0 += wv * A[cidx * 24 + d0];
            s1 += wv * A[cidx * 24 + d0 + 1];
        }
        W2h[((long)b * CC + o) * 96 + h * 12 + jj] = pkh(s0, s1);
    }
}

// ---------------------------------------------------------------------------
extern "C" void kernel_launch(void* const* d_in, const int* in_sizes, int n_in,
                              void* d_out, int out_size)
{
    const float* x      = (const float*)d_in[0];
    const float* w_qkv  = (const float*)d_in[1];
    const float* w_dw   = (const float*)d_in[2];
    const float* w_proj = (const float*)d_in[3];
    const float* temp   = (const float*)d_in[4];
    float* out = (float*)d_out;

    __half *qkv_pre, *qkv_post;
    unsigned *wh, *W2h;
    float *sumsq, *Spart;
    cudaGetSymbolAddress((void**)&qkv_pre,  g_qkv_pre);
    cudaGetSymbolAddress((void**)&qkv_post, g_qkv_post);
    cudaGetSymbolAddress((void**)&wh,       g_wh);
    cudaGetSymbolAddress((void**)&W2h,      g_W2h);
    cudaGetSymbolAddress((void**)&sumsq,    g_sumsq);
    cudaGetSymbolAddress((void**)&Spart,    g_Spart);

    const int SMEM = (96 * BST + 2 * 64 * AST) * 4;  // 103424 B
    cudaFuncSetAttribute(gemm_nres,
                         cudaFuncAttributeMaxDynamicSharedMemorySize, SMEM);

    presplit_w<<<(576 * 96 + 255) / 256, 256>>>(w_qkv, wh);

    // K1: qkv = w_qkv @ x  -> fp16 (B resident, double-buffered A)
    gemm_nres<<<dim3(HW / 128, NB), 256, SMEM>>>(
        wh, 0L, x, (long)CC * HW, qkv_pre, (long)C3 * HW, C3, HW, 2, 1);

    // K2: depthwise conv (plane-in-smem) + block-reduced sumsq
    dwconv_plane<<<dim3(C3, NB), 256>>>(qkv_pre, w_dw, qkv_post, sumsq);

    // K3: q.k^T, 3x3 tile, all-thread
    qk_kernel<<<dim3(QKCH, 64), 256>>>(qkv_post, Spart);

    // K4: per-(b,h) normalize + softmax + fold -> packed fp16 W2
    softmax_fold_kernel<<<64, 256>>>(Spart, sumsq, temp, w_proj, W2h);

    // K5: out = W2 @ v  (B = v resident fp16), fp32 out
    gemm_nres<<<dim3(HW / 128, NB), 256, SMEM>>>(
        W2h, (long)CC * 96, qkv_post + 384L * HW, (long)C3 * HW,
        out, (long)CC * HW, CC, HW, 1, 0);
}